// round 1
// baseline (speedup 1.0000x reference)
#include <cuda_runtime.h>
#include <cuda_bf16.h>
#include <cstdint>

// Problem constants
#define T_LEN 2048
#define BATCH 64
#define IDIM  256
#define HDIM  256
#define G3    (3 * HDIM)            // 768
#define M_TOT (T_LEN * BATCH)       // 131072

// 384 MB scratch for gx = x @ W_ih^T + b_ih, layout [T*B, 3H]
__device__ float g_gx[(size_t)M_TOT * G3];

// ---------------------------------------------------------------------------
// fp32 tiled GEMM (NT): C[m,n] = sum_k A[m,k] * W[n,k] + bias[n]
// A = x [M, 256] row-major, W = W_ih [768, 256] row-major.
// Tile 128(M) x 64(N) x 16(K), 256 threads, 8x4 per-thread microtile.
// ---------------------------------------------------------------------------
#define BM 128
#define BN 64
#define BK 16

__global__ __launch_bounds__(256, 2)
void indgru_gemm_kernel(const float* __restrict__ A,
                        const float* __restrict__ W,
                        const float* __restrict__ bias)
{
    __shared__ float As[BK][BM + 4];   // row stride 132 floats (528B, 16B-aligned)
    __shared__ float Bs[BK][BN + 4];   // row stride 68 floats  (272B, 16B-aligned)

    const int tid = threadIdx.x;
    const int bm  = blockIdx.y * BM;
    const int bn  = blockIdx.x * BN;
    const int tx  = tid & 15;          // n direction (16 * 4 = 64)
    const int ty  = tid >> 4;          // m direction (16 * 8 = 128)

    float acc[8][4];
    #pragma unroll
    for (int i = 0; i < 8; ++i)
        #pragma unroll
        for (int j = 0; j < 4; ++j)
            acc[i][j] = 0.0f;

    for (int kt = 0; kt < IDIM; kt += BK) {
        // Load A tile: 128 x 16 = 512 float4, 2 per thread, transposed scatter
        #pragma unroll
        for (int j = 0; j < 2; ++j) {
            int f   = tid * 2 + j;         // 0..511
            int row = f >> 2;              // 0..127
            int kq  = (f & 3) * 4;         // 0,4,8,12
            float4 v = *reinterpret_cast<const float4*>(
                A + (size_t)(bm + row) * IDIM + kt + kq);
            As[kq + 0][row] = v.x;
            As[kq + 1][row] = v.y;
            As[kq + 2][row] = v.z;
            As[kq + 3][row] = v.w;
        }
        // Load B tile: 64 x 16 = 256 float4, 1 per thread
        {
            int f   = tid;
            int row = f >> 2;              // 0..63
            int kq  = (f & 3) * 4;
            float4 v = *reinterpret_cast<const float4*>(
                W + (size_t)(bn + row) * IDIM + kt + kq);
            Bs[kq + 0][row] = v.x;
            Bs[kq + 1][row] = v.y;
            Bs[kq + 2][row] = v.z;
            Bs[kq + 3][row] = v.w;
        }
        __syncthreads();

        #pragma unroll
        for (int k = 0; k < BK; ++k) {
            float a[8], b[4];
            #pragma unroll
            for (int i = 0; i < 8; ++i) a[i] = As[k][ty * 8 + i];
            #pragma unroll
            for (int j = 0; j < 4; ++j) b[j] = Bs[k][tx * 4 + j];
            #pragma unroll
            for (int i = 0; i < 8; ++i)
                #pragma unroll
                for (int j = 0; j < 4; ++j)
                    acc[i][j] = fmaf(a[i], b[j], acc[i][j]);
        }
        __syncthreads();
    }

    // Epilogue: add b_ih, vector store to gx
    const int n = bn + tx * 4;
    float4 bv = *reinterpret_cast<const float4*>(bias + n);
    #pragma unroll
    for (int i = 0; i < 8; ++i) {
        int m = bm + ty * 8 + i;
        float4 o;
        o.x = acc[i][0] + bv.x;
        o.y = acc[i][1] + bv.y;
        o.z = acc[i][2] + bv.z;
        o.w = acc[i][3] + bv.w;
        *reinterpret_cast<float4*>(g_gx + (size_t)m * G3 + n) = o;
    }
}

// ---------------------------------------------------------------------------
// Sequential scan: one thread per (b,h) chain. Prefetch 8 timesteps of the
// 3 gate pre-activations (24 independent LDGs in flight), then run 8 fused
// GRU steps. tanh.approx.f32 for both sigmoid and tanh (MUFU).
// ---------------------------------------------------------------------------
__device__ __forceinline__ float tanh_fast(float x) {
    float y;
    asm("tanh.approx.f32 %0, %1;" : "=f"(y) : "f"(x));
    return y;
}
__device__ __forceinline__ float sigmoid_fast(float x) {
    return fmaf(tanh_fast(0.5f * x), 0.5f, 0.5f);
}

#define SCAN_UNROLL 8

__global__ __launch_bounds__(128, 8)
void indgru_scan_kernel(const float* __restrict__ b_hh,
                        const float* __restrict__ w_hh,
                        float* __restrict__ out)
{
    const int idx = blockIdx.x * blockDim.x + threadIdx.x;  // 0..16383
    const int b = idx >> 8;        // batch
    const int h = idx & (HDIM - 1);

    const float w_hr = w_hh[h];
    const float w_hz = w_hh[HDIM + h];
    const float w_hn = w_hh[2 * HDIM + h];
    const float b_hr = b_hh[h];
    const float b_hz = b_hh[HDIM + h];
    const float b_hn = b_hh[2 * HDIM + h];

    const float* p  = g_gx + (size_t)b * G3 + h;   // + t * (BATCH*G3)
    float*       po = out + (size_t)b * HDIM + h;  // + t * (BATCH*HDIM)

    const size_t GX_STRIDE  = (size_t)BATCH * G3;    // 49152
    const size_t OUT_STRIDE = (size_t)BATCH * HDIM;  // 16384

    float hv = 0.0f;

    for (int t0 = 0; t0 < T_LEN; t0 += SCAN_UNROLL) {
        float xr[SCAN_UNROLL], xz[SCAN_UNROLL], xn[SCAN_UNROLL];
        #pragma unroll
        for (int u = 0; u < SCAN_UNROLL; ++u) {
            const float* q = p + (size_t)(t0 + u) * GX_STRIDE;
            xr[u] = q[0];
            xz[u] = q[HDIM];
            xn[u] = q[2 * HDIM];
        }
        #pragma unroll
        for (int u = 0; u < SCAN_UNROLL; ++u) {
            float r = sigmoid_fast(xr[u] + fmaf(w_hr, hv, b_hr));
            float z = sigmoid_fast(xz[u] + fmaf(w_hz, hv, b_hz));
            float n = tanh_fast(fmaf(r, fmaf(w_hn, hv, b_hn), xn[u]));
            hv = fmaf(z, hv - n, n);   // (1-z)*n + z*h = n + z*(h-n)
            po[(size_t)(t0 + u) * OUT_STRIDE] = hv;
        }
    }
    // h_n appended after out
    out[(size_t)T_LEN * OUT_STRIDE + (size_t)b * HDIM + h] = hv;
}

// ---------------------------------------------------------------------------
// Launch
// ---------------------------------------------------------------------------
extern "C" void kernel_launch(void* const* d_in, const int* in_sizes, int n_in,
                              void* d_out, int out_size)
{
    const float* x    = (const float*)d_in[0];   // [T, B, I]
    const float* W_ih = (const float*)d_in[1];   // [3H, I]
    const float* b_ih = (const float*)d_in[2];   // [3H]
    const float* b_hh = (const float*)d_in[3];   // [3H]
    const float* w_hh = (const float*)d_in[4];   // [3, H]
    float* out = (float*)d_out;                  // [T,B,H] ++ [1,B,H]

    dim3 gemm_grid(G3 / BN, M_TOT / BM);         // (12, 1024)
    indgru_gemm_kernel<<<gemm_grid, 256>>>(x, W_ih, b_ih);

    indgru_scan_kernel<<<128, 128>>>(b_hh, w_hh, out);
}

// round 3
// speedup vs baseline: 2.2143x; 2.2143x over previous
#include <cuda_runtime.h>
#include <cuda_bf16.h>
#include <cstdint>

// Problem constants
#define T_LEN 2048
#define BATCH 64
#define IDIM  256
#define HDIM  256
#define G3    (3 * HDIM)            // 768
#define M_TOT (T_LEN * BATCH)       // 131072

// 402 MB scratch for gx = x @ W_ih^T + b_ih, layout [T*B, 3H]
__device__ float g_gx[(size_t)M_TOT * G3];

// ---------------------------------------------------------------------------
// HMMA bf16-split GEMM: gx[m,n] = sum_k x[m,k] * W[n,k] + bias[n]
// CTA tile 128(M) x 64(N) x 32(K). 256 threads = 8 warps (4 m x 2 n),
// warp tile 32x32. mma.sync m16n8k16 bf16->fp32, ldmatrix from padded smem.
// ---------------------------------------------------------------------------
#define BM 128
#define BN 64
#define BK 32
#define ROWH 40      // halves per smem row: 32 data + 8 pad
#define ROWB 80      // bytes per smem row (stride 80B: 8 rows cover all banks)

__device__ __forceinline__ uint32_t smem_u32(const void* p) {
    uint32_t a;
    asm("{ .reg .u64 t; cvta.to.shared.u64 t, %1; cvt.u32.u64 %0, t; }" : "=r"(a) : "l"(p));
    return a;
}

#define LDSM_X4(r0, r1, r2, r3, addr) \
    asm volatile("ldmatrix.sync.aligned.m8n8.x4.shared.b16 {%0,%1,%2,%3}, [%4];" \
                 : "=r"(r0), "=r"(r1), "=r"(r2), "=r"(r3) : "r"(addr))

#define MMA_BF16(c, a, b0, b1) \
    asm volatile("mma.sync.aligned.m16n8k16.row.col.f32.bf16.bf16.f32 " \
                 "{%0,%1,%2,%3}, {%4,%5,%6,%7}, {%8,%9}, {%0,%1,%2,%3};" \
                 : "+f"((c)[0]), "+f"((c)[1]), "+f"((c)[2]), "+f"((c)[3]) \
                 : "r"((a)[0]), "r"((a)[1]), "r"((a)[2]), "r"((a)[3]), \
                   "r"(b0), "r"(b1))

__device__ __forceinline__ uint32_t pack_bf2(float x, float y) {
    __nv_bfloat162 t = __floats2bfloat162_rn(x, y);
    return *reinterpret_cast<uint32_t*>(&t);
}

__global__ __launch_bounds__(256, 2)
void indgru_gemm_hmma(const float* __restrict__ A,
                      const float* __restrict__ W,
                      const float* __restrict__ bias)
{
    __shared__ __align__(16) __nv_bfloat16 sAh[BM * ROWH];
    __shared__ __align__(16) __nv_bfloat16 sAl[BM * ROWH];
    __shared__ __align__(16) __nv_bfloat16 sBh[BN * ROWH];
    __shared__ __align__(16) __nv_bfloat16 sBl[BN * ROWH];

    const int tid    = threadIdx.x;
    const int lane   = tid & 31;
    const int wid    = tid >> 5;
    const int warp_m = wid & 3;     // 0..3  -> 32-row band
    const int warp_n = wid >> 2;    // 0..1  -> 32-col band
    const int bm = blockIdx.y * BM;
    const int bn = blockIdx.x * BN;

    const uint32_t uAh = smem_u32(sAh);
    const uint32_t uAl = smem_u32(sAl);
    const uint32_t uBh = smem_u32(sBh);
    const uint32_t uBl = smem_u32(sBl);

    // ldmatrix per-lane address components
    // A (x4, one 16x16 tile): lanes 0-15 -> rows, lanes 16-31 -> rows at k+8
    const uint32_t a_row = warp_m * 32 + (lane & 15);
    const uint32_t a_koff = (lane >> 4) * 8;           // halves
    // B (x4, two n8k16 tiles): sub = lane>>3: bit0 -> k+8, bit1 -> next n-tile
    const uint32_t b_row = warp_n * 32 + ((lane >> 4) & 1) * 8 + (lane & 7);
    const uint32_t b_koff = ((lane >> 3) & 1) * 8;

    float c[2][4][4];
    #pragma unroll
    for (int mt = 0; mt < 2; ++mt)
        #pragma unroll
        for (int nt = 0; nt < 4; ++nt)
            #pragma unroll
            for (int q = 0; q < 4; ++q)
                c[mt][nt][q] = 0.0f;

    for (int kt = 0; kt < IDIM; kt += BK) {
        __syncthreads();
        // ---- stage A: 128x32 fp32 -> bf16 hi/lo (4 float4 per thread) ----
        #pragma unroll
        for (int i = 0; i < 4; ++i) {
            const int f   = tid + i * 256;        // 0..1023
            const int row = f >> 3;               // 0..127
            const int kq  = (f & 7) * 4;          // 0..28
            float4 v = *reinterpret_cast<const float4*>(
                A + (size_t)(bm + row) * IDIM + kt + kq);
            float hx = __bfloat162float(__float2bfloat16_rn(v.x));
            float hy = __bfloat162float(__float2bfloat16_rn(v.y));
            float hz = __bfloat162float(__float2bfloat16_rn(v.z));
            float hw = __bfloat162float(__float2bfloat16_rn(v.w));
            const uint32_t off = row * ROWB + kq * 2;
            *reinterpret_cast<uint2*>(reinterpret_cast<char*>(sAh) + off) =
                make_uint2(pack_bf2(v.x, v.y), pack_bf2(v.z, v.w));
            *reinterpret_cast<uint2*>(reinterpret_cast<char*>(sAl) + off) =
                make_uint2(pack_bf2(v.x - hx, v.y - hy), pack_bf2(v.z - hz, v.w - hw));
        }
        // ---- stage B: 64x32 fp32 -> bf16 hi/lo (2 float4 per thread) ----
        #pragma unroll
        for (int i = 0; i < 2; ++i) {
            const int f   = tid + i * 256;        // 0..511
            const int row = f >> 3;               // 0..63
            const int kq  = (f & 7) * 4;
            float4 v = *reinterpret_cast<const float4*>(
                W + (size_t)(bn + row) * IDIM + kt + kq);
            float hx = __bfloat162float(__float2bfloat16_rn(v.x));
            float hy = __bfloat162float(__float2bfloat16_rn(v.y));
            float hz = __bfloat162float(__float2bfloat16_rn(v.z));
            float hw = __bfloat162float(__float2bfloat16_rn(v.w));
            const uint32_t off = row * ROWB + kq * 2;
            *reinterpret_cast<uint2*>(reinterpret_cast<char*>(sBh) + off) =
                make_uint2(pack_bf2(v.x, v.y), pack_bf2(v.z, v.w));
            *reinterpret_cast<uint2*>(reinterpret_cast<char*>(sBl) + off) =
                make_uint2(pack_bf2(v.x - hx, v.y - hy), pack_bf2(v.z - hz, v.w - hw));
        }
        __syncthreads();

        // ---- compute: 2 k16 steps ----
        #pragma unroll
        for (int ks = 0; ks < 2; ++ks) {
            const uint32_t kh = ks * 16;   // halves
            uint32_t ah[2][4], al[2][4];
            #pragma unroll
            for (int mt = 0; mt < 2; ++mt) {
                const uint32_t ao = (a_row + mt * 16) * ROWB + (kh + a_koff) * 2;
                LDSM_X4(ah[mt][0], ah[mt][1], ah[mt][2], ah[mt][3], uAh + ao);
                LDSM_X4(al[mt][0], al[mt][1], al[mt][2], al[mt][3], uAl + ao);
            }
            uint32_t bh[8], bl[8];
            #pragma unroll
            for (int j = 0; j < 2; ++j) {
                const uint32_t bo = (b_row + j * 16) * ROWB + (kh + b_koff) * 2;
                LDSM_X4(bh[j*4+0], bh[j*4+1], bh[j*4+2], bh[j*4+3], uBh + bo);
                LDSM_X4(bl[j*4+0], bl[j*4+1], bl[j*4+2], bl[j*4+3], uBl + bo);
            }
            #pragma unroll
            for (int mt = 0; mt < 2; ++mt)
                #pragma unroll
                for (int nt = 0; nt < 4; ++nt) {
                    MMA_BF16(c[mt][nt], ah[mt], bh[nt*2], bh[nt*2+1]);
                    MMA_BF16(c[mt][nt], ah[mt], bl[nt*2], bl[nt*2+1]);
                    MMA_BF16(c[mt][nt], al[mt], bh[nt*2], bh[nt*2+1]);
                }
        }
    }

    // ---- epilogue: add bias, store fp32 to g_gx ----
    #pragma unroll
    for (int mt = 0; mt < 2; ++mt) {
        const int row0 = bm + warp_m * 32 + mt * 16 + (lane >> 2);
        #pragma unroll
        for (int nt = 0; nt < 4; ++nt) {
            const int n0 = bn + warp_n * 32 + nt * 8 + (lane & 3) * 2;
            const float bv0 = bias[n0];
            const float bv1 = bias[n0 + 1];
            float2 o0 = make_float2(c[mt][nt][0] + bv0, c[mt][nt][1] + bv1);
            float2 o1 = make_float2(c[mt][nt][2] + bv0, c[mt][nt][3] + bv1);
            *reinterpret_cast<float2*>(g_gx + (size_t)row0 * G3 + n0) = o0;
            *reinterpret_cast<float2*>(g_gx + (size_t)(row0 + 8) * G3 + n0) = o1;
        }
    }
}

// ---------------------------------------------------------------------------
// Sequential scan with software-pipelined prefetch (16 steps ahead).
// ---------------------------------------------------------------------------
__device__ __forceinline__ float tanh_fast(float x) {
    float y;
    asm("tanh.approx.f32 %0, %1;" : "=f"(y) : "f"(x));
    return y;
}
__device__ __forceinline__ float sigmoid_fast(float x) {
    return fmaf(tanh_fast(0.5f * x), 0.5f, 0.5f);
}

#define SU 16

__global__ __launch_bounds__(128, 4)
void indgru_scan_kernel(const float* __restrict__ b_hh,
                        const float* __restrict__ w_hh,
                        float* __restrict__ out)
{
    const int idx = blockIdx.x * blockDim.x + threadIdx.x;  // 0..16383
    const int b = idx >> 8;
    const int h = idx & (HDIM - 1);

    const float w_hr = w_hh[h];
    const float w_hz = w_hh[HDIM + h];
    const float w_hn = w_hh[2 * HDIM + h];
    const float b_hr = b_hh[h];
    const float b_hz = b_hh[HDIM + h];
    const float b_hn = b_hh[2 * HDIM + h];

    const float* p  = g_gx + (size_t)b * G3 + h;
    float*       po = out + (size_t)b * HDIM + h;
    const size_t GX_STRIDE  = (size_t)BATCH * G3;    // 49152
    const size_t OUT_STRIDE = (size_t)BATCH * HDIM;  // 16384

    float cxr[SU], cxz[SU], cxn[SU];
    float nxr[SU], nxz[SU], nxn[SU];

    #pragma unroll
    for (int u = 0; u < SU; ++u) {
        const float* q = p + (size_t)u * GX_STRIDE;
        cxr[u] = q[0]; cxz[u] = q[HDIM]; cxn[u] = q[2 * HDIM];
    }

    float hv = 0.0f;

    #pragma unroll 1
    for (int t0 = 0; t0 < T_LEN; t0 += SU) {
        if (t0 + SU < T_LEN) {
            #pragma unroll
            for (int u = 0; u < SU; ++u) {
                const float* q = p + (size_t)(t0 + SU + u) * GX_STRIDE;
                nxr[u] = q[0]; nxz[u] = q[HDIM]; nxn[u] = q[2 * HDIM];
            }
        }
        #pragma unroll
        for (int u = 0; u < SU; ++u) {
            float r = sigmoid_fast(cxr[u] + fmaf(w_hr, hv, b_hr));
            float z = sigmoid_fast(cxz[u] + fmaf(w_hz, hv, b_hz));
            float n = tanh_fast(fmaf(r, fmaf(w_hn, hv, b_hn), cxn[u]));
            hv = fmaf(z, hv - n, n);
            po[(size_t)(t0 + u) * OUT_STRIDE] = hv;
        }
        #pragma unroll
        for (int u = 0; u < SU; ++u) {
            cxr[u] = nxr[u]; cxz[u] = nxz[u]; cxn[u] = nxn[u];
        }
    }
    out[(size_t)T_LEN * OUT_STRIDE + (size_t)b * HDIM + h] = hv;
}

// ---------------------------------------------------------------------------
// Launch
// ---------------------------------------------------------------------------
extern "C" void kernel_launch(void* const* d_in, const int* in_sizes, int n_in,
                              void* d_out, int out_size)
{
    const float* x    = (const float*)d_in[0];   // [T, B, I]
    const float* W_ih = (const float*)d_in[1];   // [3H, I]
    const float* b_ih = (const float*)d_in[2];   // [3H]
    const float* b_hh = (const float*)d_in[3];   // [3H]
    const float* w_hh = (const float*)d_in[4];   // [3, H]
    float* out = (float*)d_out;

    dim3 gemm_grid(G3 / BN, M_TOT / BM);         // (12, 1024)
    indgru_gemm_hmma<<<gemm_grid, 256>>>(x, W_ih, b_ih);

    indgru_scan_kernel<<<128, 128>>>(b_hh, w_hh, out);
}

// round 4
// speedup vs baseline: 2.9120x; 1.3150x over previous
#include <cuda_runtime.h>
#include <cuda_fp16.h>
#include <cstdint>

// Problem constants
#define T_LEN 2048
#define BATCH 64
#define IDIM  256
#define HDIM  256
#define G3    (3 * HDIM)            // 768
#define M_TOT (T_LEN * BATCH)       // 131072

// 402 MB scratch for gx = x @ W_ih^T + b_ih, layout [T*B, 3H]
__device__ float g_gx[(size_t)M_TOT * G3];

// ---------------------------------------------------------------------------
// HMMA fp16 2-term split GEMM: gx[m,n] = sum_k x[m,k] * W[n,k] + bias[n]
// A = Ah + Al (fp16 hi/lo, ~22 bits), B = single fp16 (error 2^-12).
// C += Ah*B + Al*B.  CTA tile 128x64x32, 8 warps (4m x 2n), warp tile 32x32.
// Register-prefetch of next k-tile's global loads overlaps the MMA phase.
// ---------------------------------------------------------------------------
#define BM 128
#define BN 64
#define BK 32
#define ROWH 40      // halves per smem row: 32 data + 8 pad
#define ROWB 80      // bytes per smem row

__device__ __forceinline__ uint32_t smem_u32(const void* p) {
    uint32_t a;
    asm("{ .reg .u64 t; cvta.to.shared.u64 t, %1; cvt.u32.u64 %0, t; }" : "=r"(a) : "l"(p));
    return a;
}

#define LDSM_X4(r0, r1, r2, r3, addr) \
    asm volatile("ldmatrix.sync.aligned.m8n8.x4.shared.b16 {%0,%1,%2,%3}, [%4];" \
                 : "=r"(r0), "=r"(r1), "=r"(r2), "=r"(r3) : "r"(addr))

#define MMA_F16(c, a, b0, b1) \
    asm volatile("mma.sync.aligned.m16n8k16.row.col.f32.f16.f16.f32 " \
                 "{%0,%1,%2,%3}, {%4,%5,%6,%7}, {%8,%9}, {%0,%1,%2,%3};" \
                 : "+f"((c)[0]), "+f"((c)[1]), "+f"((c)[2]), "+f"((c)[3]) \
                 : "r"((a)[0]), "r"((a)[1]), "r"((a)[2]), "r"((a)[3]), \
                   "r"(b0), "r"(b1))

__device__ __forceinline__ uint32_t pack_h2(float x, float y) {
    __half2 t = __floats2half2_rn(x, y);
    return *reinterpret_cast<uint32_t*>(&t);
}

__global__ __launch_bounds__(256, 2)
void indgru_gemm_hmma(const float* __restrict__ A,
                      const float* __restrict__ W,
                      const float* __restrict__ bias)
{
    __shared__ __align__(16) __half sAh[BM * ROWH];
    __shared__ __align__(16) __half sAl[BM * ROWH];
    __shared__ __align__(16) __half sB [BN * ROWH];

    const int tid    = threadIdx.x;
    const int lane   = tid & 31;
    const int wid    = tid >> 5;
    const int warp_m = wid & 3;
    const int warp_n = wid >> 2;
    const int bm = blockIdx.y * BM;
    const int bn = blockIdx.x * BN;

    const uint32_t uAh = smem_u32(sAh);
    const uint32_t uAl = smem_u32(sAl);
    const uint32_t uB  = smem_u32(sB);

    // ldmatrix per-lane address components (same mapping as verified R3 kernel)
    const uint32_t a_row  = warp_m * 32 + (lane & 15);
    const uint32_t a_koff = (lane >> 4) * 8;
    const uint32_t b_row  = warp_n * 32 + ((lane >> 4) & 1) * 8 + (lane & 7);
    const uint32_t b_koff = ((lane >> 3) & 1) * 8;

    // staging index precompute
    const int a_rows[4] = { (tid + 0)   >> 3, (tid + 256) >> 3,
                            (tid + 512) >> 3, (tid + 768) >> 3 };
    const int a_kq = (tid & 7) * 4;
    const int b_rows[2] = { tid >> 3, (tid + 256) >> 3 };

    float c[2][4][4];
    #pragma unroll
    for (int mt = 0; mt < 2; ++mt)
        #pragma unroll
        for (int nt = 0; nt < 4; ++nt)
            #pragma unroll
            for (int q = 0; q < 4; ++q)
                c[mt][nt][q] = 0.0f;

    // prefetch k-tile 0 into registers
    float4 pa[4], pb[2];
    #pragma unroll
    for (int i = 0; i < 4; ++i)
        pa[i] = *reinterpret_cast<const float4*>(A + (size_t)(bm + a_rows[i]) * IDIM + a_kq);
    #pragma unroll
    for (int i = 0; i < 2; ++i)
        pb[i] = *reinterpret_cast<const float4*>(W + (size_t)(bn + b_rows[i]) * IDIM + a_kq);

    for (int kt = 0; kt < IDIM; kt += BK) {
        // ---- convert & store staged registers ----
        #pragma unroll
        for (int i = 0; i < 4; ++i) {
            float4 v = pa[i];
            float hx = __half2float(__float2half_rn(v.x));
            float hy = __half2float(__float2half_rn(v.y));
            float hz = __half2float(__float2half_rn(v.z));
            float hw = __half2float(__float2half_rn(v.w));
            const uint32_t off = a_rows[i] * ROWB + a_kq * 2;
            *reinterpret_cast<uint2*>(reinterpret_cast<char*>(sAh) + off) =
                make_uint2(pack_h2(v.x, v.y), pack_h2(v.z, v.w));
            *reinterpret_cast<uint2*>(reinterpret_cast<char*>(sAl) + off) =
                make_uint2(pack_h2(v.x - hx, v.y - hy), pack_h2(v.z - hz, v.w - hw));
        }
        #pragma unroll
        for (int i = 0; i < 2; ++i) {
            float4 v = pb[i];
            const uint32_t off = b_rows[i] * ROWB + a_kq * 2;
            *reinterpret_cast<uint2*>(reinterpret_cast<char*>(sB) + off) =
                make_uint2(pack_h2(v.x, v.y), pack_h2(v.z, v.w));
        }
        __syncthreads();

        // ---- prefetch next k-tile (overlaps with MMA below) ----
        if (kt + BK < IDIM) {
            const int kn = kt + BK;
            #pragma unroll
            for (int i = 0; i < 4; ++i)
                pa[i] = *reinterpret_cast<const float4*>(
                    A + (size_t)(bm + a_rows[i]) * IDIM + kn + a_kq);
            #pragma unroll
            for (int i = 0; i < 2; ++i)
                pb[i] = *reinterpret_cast<const float4*>(
                    W + (size_t)(bn + b_rows[i]) * IDIM + kn + a_kq);
        }

        // ---- compute: 2 k16 steps ----
        #pragma unroll
        for (int ks = 0; ks < 2; ++ks) {
            const uint32_t kh = ks * 16;
            uint32_t ah[2][4], al[2][4];
            #pragma unroll
            for (int mt = 0; mt < 2; ++mt) {
                const uint32_t ao = (a_row + mt * 16) * ROWB + (kh + a_koff) * 2;
                LDSM_X4(ah[mt][0], ah[mt][1], ah[mt][2], ah[mt][3], uAh + ao);
                LDSM_X4(al[mt][0], al[mt][1], al[mt][2], al[mt][3], uAl + ao);
            }
            uint32_t b[8];
            #pragma unroll
            for (int j = 0; j < 2; ++j) {
                const uint32_t bo = (b_row + j * 16) * ROWB + (kh + b_koff) * 2;
                LDSM_X4(b[j*4+0], b[j*4+1], b[j*4+2], b[j*4+3], uB + bo);
            }
            #pragma unroll
            for (int mt = 0; mt < 2; ++mt)
                #pragma unroll
                for (int nt = 0; nt < 4; ++nt) {
                    MMA_F16(c[mt][nt], ah[mt], b[nt*2], b[nt*2+1]);
                    MMA_F16(c[mt][nt], al[mt], b[nt*2], b[nt*2+1]);
                }
        }
        __syncthreads();
    }

    // ---- epilogue: add bias, store fp32 to g_gx ----
    #pragma unroll
    for (int mt = 0; mt < 2; ++mt) {
        const int row0 = bm + warp_m * 32 + mt * 16 + (lane >> 2);
        #pragma unroll
        for (int nt = 0; nt < 4; ++nt) {
            const int n0 = bn + warp_n * 32 + nt * 8 + (lane & 3) * 2;
            const float bv0 = bias[n0];
            const float bv1 = bias[n0 + 1];
            float2 o0 = make_float2(c[mt][nt][0] + bv0, c[mt][nt][1] + bv1);
            float2 o1 = make_float2(c[mt][nt][2] + bv0, c[mt][nt][3] + bv1);
            *reinterpret_cast<float2*>(g_gx + (size_t)row0 * G3 + n0) = o0;
            *reinterpret_cast<float2*>(g_gx + (size_t)(row0 + 8) * G3 + n0) = o1;
        }
    }
}

// ---------------------------------------------------------------------------
// Scan: bulk-synchronous producer/consumer.
// 128 blocks x 256 threads. Threads 0-127: one chain each (block covers
// 128 consecutive (b,h) pairs). Threads 128-255: stream gx 16 steps ahead
// into a double-buffered smem ring with coalesced float4 loads.
// ---------------------------------------------------------------------------
__device__ __forceinline__ float tanh_fast(float x) {
    float y;
    asm("tanh.approx.f32 %0, %1;" : "=f"(y) : "f"(x));
    return y;
}

#define SB_STEPS 16

__global__ __launch_bounds__(256, 1)
void indgru_scan_kernel(const float* __restrict__ b_hh,
                        const float* __restrict__ w_hh,
                        float* __restrict__ out)
{
    __shared__ __align__(16) float sbuf[2][SB_STEPS][3][128];

    const int tid = threadIdx.x;
    const int bid = blockIdx.x;                  // 0..127
    const int b  = bid >> 1;                     // batch
    const int h0 = (bid & 1) << 7;               // 0 or 128
    const size_t GXS = (size_t)BATCH * G3;       // 49152
    const size_t OS  = (size_t)BATCH * HDIM;     // 16384

    if (tid >= 128) {
        // ------------------ producer ------------------
        const int pt = tid - 128;
        const int q  = pt & 31;                  // float4 lane
        const int w  = pt >> 5;                  // warp 0..3 -> steps [4w, 4w+4)
        const float* gbase = g_gx + (size_t)b * G3 + h0 + q * 4;

        // prologue: fill buffer 0 with steps 0..15
        #pragma unroll
        for (int j = 0; j < 12; ++j) {
            const int u = w * 4 + j / 3;
            const int g = j % 3;
            float4 v = *reinterpret_cast<const float4*>(
                gbase + (size_t)u * GXS + g * HDIM);
            *reinterpret_cast<float4*>(&sbuf[0][u][g][q * 4]) = v;
        }
        __syncthreads();

        for (int t0 = 0; t0 < T_LEN; t0 += SB_STEPS) {
            const int nb = ((t0 >> 4) & 1) ^ 1;      // buffer to fill
            if (t0 + SB_STEPS < T_LEN) {
                #pragma unroll
                for (int j = 0; j < 12; ++j) {
                    const int u = w * 4 + j / 3;
                    const int g = j % 3;
                    float4 v = *reinterpret_cast<const float4*>(
                        gbase + (size_t)(t0 + SB_STEPS + u) * GXS + g * HDIM);
                    *reinterpret_cast<float4*>(&sbuf[nb][u][g][q * 4]) = v;
                }
            }
            __syncthreads();
        }
    } else {
        // ------------------ consumer ------------------
        const int i = tid;                       // 0..127
        const int h = h0 + i;

        const float whr_h = 0.5f * w_hh[h];
        const float whz_h = 0.5f * w_hh[HDIM + h];
        const float w_hn  = w_hh[2 * HDIM + h];
        const float bhr_h = 0.5f * b_hh[h];
        const float bhz_h = 0.5f * b_hh[HDIM + h];
        const float b_hn  = b_hh[2 * HDIM + h];

        float* po = out + (size_t)b * HDIM + h;
        float hv = 0.0f;

        __syncthreads();                          // wait for buffer 0

        for (int t0 = 0; t0 < T_LEN; t0 += SB_STEPS) {
            const int cb = (t0 >> 4) & 1;
            #pragma unroll
            for (int u = 0; u < SB_STEPS; ++u) {
                const float xr = sbuf[cb][u][0][i];
                const float xz = sbuf[cb][u][1][i];
                const float xn = sbuf[cb][u][2][i];
                const float pr = fmaf(0.5f, xr, bhr_h);       // off critical path
                const float pz = fmaf(0.5f, xz, bhz_h);
                const float kk = fmaf(w_hn, hv, b_hn);
                const float r = fmaf(tanh_fast(fmaf(whr_h, hv, pr)), 0.5f, 0.5f);
                const float z = fmaf(tanh_fast(fmaf(whz_h, hv, pz)), 0.5f, 0.5f);
                const float n = tanh_fast(fmaf(r, kk, xn));
                hv = fmaf(z, hv - n, n);
                po[(size_t)(t0 + u) * OS] = hv;
            }
            __syncthreads();
        }
        // h_n appended after out
        out[(size_t)T_LEN * OS + (size_t)b * HDIM + h] = hv;
    }
}

// ---------------------------------------------------------------------------
// Launch
// ---------------------------------------------------------------------------
extern "C" void kernel_launch(void* const* d_in, const int* in_sizes, int n_in,
                              void* d_out, int out_size)
{
    const float* x    = (const float*)d_in[0];   // [T, B, I]
    const float* W_ih = (const float*)d_in[1];   // [3H, I]
    const float* b_ih = (const float*)d_in[2];   // [3H]
    const float* b_hh = (const float*)d_in[3];   // [3H]
    const float* w_hh = (const float*)d_in[4];   // [3, H]
    float* out = (float*)d_out;

    dim3 gemm_grid(G3 / BN, M_TOT / BM);         // (12, 1024)
    indgru_gemm_hmma<<<gemm_grid, 256>>>(x, W_ih, b_ih);

    indgru_scan_kernel<<<128, 256>>>(b_hh, w_hh, out);
}

// round 5
// speedup vs baseline: 3.6806x; 1.2639x over previous
#include <cuda_runtime.h>
#include <cuda_fp16.h>
#include <cstdint>

// Problem constants
#define T_LEN 2048
#define BATCH 64
#define IDIM  256
#define HDIM  256
#define G3    (3 * HDIM)            // 768
#define M_TOT (T_LEN * BATCH)       // 131072

// 402 MB scratch for gx = x @ W_ih^T + b_ih, layout [T*B, 3H]
__device__ float g_gx[(size_t)M_TOT * G3];

__device__ __forceinline__ uint32_t smem_u32(const void* p) {
    uint32_t a;
    asm("{ .reg .u64 t; cvta.to.shared.u64 t, %1; cvt.u32.u64 %0, t; }" : "=r"(a) : "l"(p));
    return a;
}

// ---------------------------------------------------------------------------
// HMMA fp16 single-term GEMM: gx[m,n] = sum_k x[m,k] * W[n,k] + bias[n]
// A and B both single fp16 (indep 2^-12 roundings -> ~3.5e-4 rel err).
// CTA tile 128x64x32, 8 warps (4m x 2n), warp tile 32x32.
// ---------------------------------------------------------------------------
#define BM 128
#define BN 64
#define BK 32
#define ROWH 40      // halves per smem row: 32 data + 8 pad
#define ROWB 80      // bytes per smem row

#define LDSM_X4(r0, r1, r2, r3, addr) \
    asm volatile("ldmatrix.sync.aligned.m8n8.x4.shared.b16 {%0,%1,%2,%3}, [%4];" \
                 : "=r"(r0), "=r"(r1), "=r"(r2), "=r"(r3) : "r"(addr))

#define MMA_F16(c, a, b0, b1) \
    asm volatile("mma.sync.aligned.m16n8k16.row.col.f32.f16.f16.f32 " \
                 "{%0,%1,%2,%3}, {%4,%5,%6,%7}, {%8,%9}, {%0,%1,%2,%3};" \
                 : "+f"((c)[0]), "+f"((c)[1]), "+f"((c)[2]), "+f"((c)[3]) \
                 : "r"((a)[0]), "r"((a)[1]), "r"((a)[2]), "r"((a)[3]), \
                   "r"(b0), "r"(b1))

__device__ __forceinline__ uint32_t pack_h2(float x, float y) {
    __half2 t = __floats2half2_rn(x, y);
    return *reinterpret_cast<uint32_t*>(&t);
}

__global__ __launch_bounds__(256, 2)
void indgru_gemm_hmma(const float* __restrict__ A,
                      const float* __restrict__ W,
                      const float* __restrict__ bias)
{
    __shared__ __align__(16) __half sA[BM * ROWH];
    __shared__ __align__(16) __half sB[BN * ROWH];

    const int tid    = threadIdx.x;
    const int lane   = tid & 31;
    const int wid    = tid >> 5;
    const int warp_m = wid & 3;
    const int warp_n = wid >> 2;
    const int bm = blockIdx.y * BM;
    const int bn = blockIdx.x * BN;

    const uint32_t uA = smem_u32(sA);
    const uint32_t uB = smem_u32(sB);

    // ldmatrix per-lane address components (mapping verified in R3/R4)
    const uint32_t a_row  = warp_m * 32 + (lane & 15);
    const uint32_t a_koff = (lane >> 4) * 8;
    const uint32_t b_row  = warp_n * 32 + ((lane >> 4) & 1) * 8 + (lane & 7);
    const uint32_t b_koff = ((lane >> 3) & 1) * 8;

    // staging index precompute
    const int a_rows[4] = { (tid + 0)   >> 3, (tid + 256) >> 3,
                            (tid + 512) >> 3, (tid + 768) >> 3 };
    const int a_kq = (tid & 7) * 4;
    const int b_rows[2] = { tid >> 3, (tid + 256) >> 3 };

    float c[2][4][4];
    #pragma unroll
    for (int mt = 0; mt < 2; ++mt)
        #pragma unroll
        for (int nt = 0; nt < 4; ++nt)
            #pragma unroll
            for (int q = 0; q < 4; ++q)
                c[mt][nt][q] = 0.0f;

    // prefetch k-tile 0 into registers
    float4 pa[4], pb[2];
    #pragma unroll
    for (int i = 0; i < 4; ++i)
        pa[i] = *reinterpret_cast<const float4*>(A + (size_t)(bm + a_rows[i]) * IDIM + a_kq);
    #pragma unroll
    for (int i = 0; i < 2; ++i)
        pb[i] = *reinterpret_cast<const float4*>(W + (size_t)(bn + b_rows[i]) * IDIM + a_kq);

    for (int kt = 0; kt < IDIM; kt += BK) {
        // ---- convert & store staged registers ----
        #pragma unroll
        for (int i = 0; i < 4; ++i) {
            float4 v = pa[i];
            const uint32_t off = a_rows[i] * ROWB + a_kq * 2;
            *reinterpret_cast<uint2*>(reinterpret_cast<char*>(sA) + off) =
                make_uint2(pack_h2(v.x, v.y), pack_h2(v.z, v.w));
        }
        #pragma unroll
        for (int i = 0; i < 2; ++i) {
            float4 v = pb[i];
            const uint32_t off = b_rows[i] * ROWB + a_kq * 2;
            *reinterpret_cast<uint2*>(reinterpret_cast<char*>(sB) + off) =
                make_uint2(pack_h2(v.x, v.y), pack_h2(v.z, v.w));
        }
        __syncthreads();

        // ---- prefetch next k-tile (overlaps with MMA below) ----
        if (kt + BK < IDIM) {
            const int kn = kt + BK;
            #pragma unroll
            for (int i = 0; i < 4; ++i)
                pa[i] = *reinterpret_cast<const float4*>(
                    A + (size_t)(bm + a_rows[i]) * IDIM + kn + a_kq);
            #pragma unroll
            for (int i = 0; i < 2; ++i)
                pb[i] = *reinterpret_cast<const float4*>(
                    W + (size_t)(bn + b_rows[i]) * IDIM + kn + a_kq);
        }

        // ---- compute: 2 k16 steps ----
        #pragma unroll
        for (int ks = 0; ks < 2; ++ks) {
            const uint32_t kh = ks * 16;
            uint32_t a[2][4];
            #pragma unroll
            for (int mt = 0; mt < 2; ++mt) {
                const uint32_t ao = (a_row + mt * 16) * ROWB + (kh + a_koff) * 2;
                LDSM_X4(a[mt][0], a[mt][1], a[mt][2], a[mt][3], uA + ao);
            }
            uint32_t b[8];
            #pragma unroll
            for (int j = 0; j < 2; ++j) {
                const uint32_t bo = (b_row + j * 16) * ROWB + (kh + b_koff) * 2;
                LDSM_X4(b[j*4+0], b[j*4+1], b[j*4+2], b[j*4+3], uB + bo);
            }
            #pragma unroll
            for (int mt = 0; mt < 2; ++mt)
                #pragma unroll
                for (int nt = 0; nt < 4; ++nt)
                    MMA_F16(c[mt][nt], a[mt], b[nt*2], b[nt*2+1]);
        }
        __syncthreads();
    }

    // ---- epilogue: add bias, store fp32 to g_gx ----
    #pragma unroll
    for (int mt = 0; mt < 2; ++mt) {
        const int row0 = bm + warp_m * 32 + mt * 16 + (lane >> 2);
        #pragma unroll
        for (int nt = 0; nt < 4; ++nt) {
            const int n0 = bn + warp_n * 32 + nt * 8 + (lane & 3) * 2;
            const float bv0 = bias[n0];
            const float bv1 = bias[n0 + 1];
            float2 o0 = make_float2(c[mt][nt][0] + bv0, c[mt][nt][1] + bv1);
            float2 o1 = make_float2(c[mt][nt][2] + bv0, c[mt][nt][3] + bv1);
            *reinterpret_cast<float2*>(g_gx + (size_t)row0 * G3 + n0) = o0;
            *reinterpret_cast<float2*>(g_gx + (size_t)(row0 + 8) * G3 + n0) = o1;
        }
    }
}

// ---------------------------------------------------------------------------
// Scan: cp.async 4-stage ring. 128 blocks x 128 threads; every thread is
// a consumer (one chain) and issues its share of the cp.async stream three
// stages ahead. wait_group 2 keeps two stages in flight at all times.
// ---------------------------------------------------------------------------
__device__ __forceinline__ float tanh_fast(float x) {
    float y;
    asm("tanh.approx.f32 %0, %1;" : "=f"(y) : "f"(x));
    return y;
}

#define SB_STEPS 16
#define NSTAGE 4
#define STAGE_FLOATS (SB_STEPS * 3 * 128)          // 6144
#define STAGE_BYTES  (STAGE_FLOATS * 4)            // 24576
#define SCAN_SMEM    (NSTAGE * STAGE_BYTES)        // 98304
#define NT (T_LEN / SB_STEPS)                      // 128

#define CP_ASYNC16(dst, src) \
    asm volatile("cp.async.cg.shared.global [%0], [%1], 16;" \
                 :: "r"(dst), "l"(src) : "memory")
#define CP_COMMIT() asm volatile("cp.async.commit_group;" ::: "memory")
#define CP_WAIT2()  asm volatile("cp.async.wait_group 2;" ::: "memory")

__global__ __launch_bounds__(128, 1)
void indgru_scan_kernel(const float* __restrict__ b_hh,
                        const float* __restrict__ w_hh,
                        float* __restrict__ out)
{
    extern __shared__ float sbuf[];   // [NSTAGE][SB_STEPS][3][128]
    const uint32_t sb = smem_u32(sbuf);

    const int tid  = threadIdx.x;     // 0..127
    const int lane = tid & 31;
    const int w    = tid >> 5;        // 0..3
    const int bid  = blockIdx.x;      // 0..127
    const int b  = bid >> 1;
    const int h0 = (bid & 1) << 7;
    const size_t GXS = (size_t)BATCH * G3;    // 49152
    const size_t OS  = (size_t)BATCH * HDIM;  // 16384

    const float* gbase = g_gx + (size_t)b * G3 + h0;

    // issue one stage's cp.async traffic (this thread's 12 x 16B)
    auto issue_stage = [&](int s, int buf) {
        const uint32_t dst0 = sb + (uint32_t)buf * STAGE_BYTES + (w * 12) * 512 + lane * 16;
        const float* src0 = gbase + (size_t)(s * SB_STEPS + w * 4) * GXS + lane * 4;
        #pragma unroll
        for (int j = 0; j < 12; ++j) {
            const int u = j / 3;              // step within this warp's quartet
            const int g = j % 3;              // gate
            CP_ASYNC16(dst0 + j * 512, src0 + (size_t)u * GXS + g * HDIM);
        }
    };

    // prologue: stages 0,1,2 in flight
    issue_stage(0, 0); CP_COMMIT();
    issue_stage(1, 1); CP_COMMIT();
    issue_stage(2, 2); CP_COMMIT();

    // chain parameters
    const int i = tid;
    const int h = h0 + i;
    const float whr_h = 0.5f * w_hh[h];
    const float whz_h = 0.5f * w_hh[HDIM + h];
    const float w_hn  = w_hh[2 * HDIM + h];
    const float bhr_h = 0.5f * b_hh[h];
    const float bhz_h = 0.5f * b_hh[HDIM + h];
    const float b_hn  = b_hh[2 * HDIM + h];

    float* po = out + (size_t)b * HDIM + h;
    float hv = 0.0f;

    #pragma unroll 1
    for (int s = 0; s < NT; ++s) {
        CP_WAIT2();                    // stage s complete (for this thread)
        __syncthreads();               // ... for all threads

        if (s + 3 < NT) issue_stage(s + 3, (s + 3) & (NSTAGE - 1));
        CP_COMMIT();                   // always commit (empty groups OK)

        const float* st = sbuf + (size_t)(s & (NSTAGE - 1)) * STAGE_FLOATS;
        #pragma unroll
        for (int u = 0; u < SB_STEPS; ++u) {
            const float xr = st[(u * 3 + 0) * 128 + i];
            const float xz = st[(u * 3 + 1) * 128 + i];
            const float xn = st[(u * 3 + 2) * 128 + i];
            const float pr = fmaf(0.5f, xr, bhr_h);   // off critical path
            const float pz = fmaf(0.5f, xz, bhz_h);
            const float kk = fmaf(w_hn, hv, b_hn);
            const float r = fmaf(tanh_fast(fmaf(whr_h, hv, pr)), 0.5f, 0.5f);
            const float z = fmaf(tanh_fast(fmaf(whz_h, hv, pz)), 0.5f, 0.5f);
            const float n = tanh_fast(fmaf(r, kk, xn));
            hv = fmaf(z, hv - n, n);
            po[(size_t)(s * SB_STEPS + u) * OS] = hv;
        }
    }
    // h_n appended after out
    out[(size_t)T_LEN * OS + (size_t)b * HDIM + h] = hv;
}

// ---------------------------------------------------------------------------
// Launch
// ---------------------------------------------------------------------------
extern "C" void kernel_launch(void* const* d_in, const int* in_sizes, int n_in,
                              void* d_out, int out_size)
{
    const float* x    = (const float*)d_in[0];   // [T, B, I]
    const float* W_ih = (const float*)d_in[1];   // [3H, I]
    const float* b_ih = (const float*)d_in[2];   // [3H]
    const float* b_hh = (const float*)d_in[3];   // [3H]
    const float* w_hh = (const float*)d_in[4];   // [3, H]
    float* out = (float*)d_out;

    static bool attr_done = false;
    if (!attr_done) {
        cudaFuncSetAttribute(indgru_scan_kernel,
                             cudaFuncAttributeMaxDynamicSharedMemorySize, SCAN_SMEM);
        attr_done = true;
    }

    dim3 gemm_grid(G3 / BN, M_TOT / BM);         // (12, 1024)
    indgru_gemm_hmma<<<gemm_grid, 256>>>(x, W_ih, b_ih);

    indgru_scan_kernel<<<128, 128, SCAN_SMEM>>>(b_hh, w_hh, out);
}

// round 6
// speedup vs baseline: 4.1781x; 1.1352x over previous
#include <cuda_runtime.h>
#include <cuda_fp16.h>
#include <cstdint>

// Problem constants
#define T_LEN 2048
#define BATCH 64
#define IDIM  256
#define HDIM  256
#define G3    (3 * HDIM)            // 768
#define M_TOT (T_LEN * BATCH)       // 131072

// Scratch: fp16 x, fp16 W, fp16 gx
__device__ __half g_xh[(size_t)M_TOT * IDIM];     // 67 MB
__device__ __half g_wh[(size_t)G3 * IDIM];        // 393 KB
__device__ __half g_gxh[(size_t)M_TOT * G3];      // 201 MB

__device__ __forceinline__ uint32_t smem_u32(const void* p) {
    uint32_t a;
    asm("{ .reg .u64 t; cvta.to.shared.u64 t, %1; cvt.u32.u64 %0, t; }" : "=r"(a) : "l"(p));
    return a;
}

__device__ __forceinline__ uint32_t pack_h2(float x, float y) {
    __half2 t = __floats2half2_rn(x, y);
    return *reinterpret_cast<uint32_t*>(&t);
}

// ---------------------------------------------------------------------------
// Convert: x (and W) fp32 -> fp16 scratch.  Grid-stride over float4 units.
// ---------------------------------------------------------------------------
#define XN4 ((size_t)M_TOT * IDIM / 4)
#define WN4 ((size_t)G3 * IDIM / 4)

__global__ __launch_bounds__(256)
void convert_kernel(const float* __restrict__ x, const float* __restrict__ W)
{
    const size_t total = XN4 + WN4;
    for (size_t i = (size_t)blockIdx.x * blockDim.x + threadIdx.x;
         i < total; i += (size_t)gridDim.x * blockDim.x) {
        if (i < XN4) {
            float4 v = reinterpret_cast<const float4*>(x)[i];
            reinterpret_cast<uint2*>(g_xh)[i] =
                make_uint2(pack_h2(v.x, v.y), pack_h2(v.z, v.w));
        } else {
            const size_t j = i - XN4;
            float4 v = reinterpret_cast<const float4*>(W)[j];
            reinterpret_cast<uint2*>(g_wh)[j] =
                make_uint2(pack_h2(v.x, v.y), pack_h2(v.z, v.w));
        }
    }
}

// ---------------------------------------------------------------------------
// HMMA fp16 GEMM, cp.async double-buffered: gxh = xh @ Wh^T + bias (fp16 out)
// CTA tile 128(M) x 128(N) x 32(K). 8 warps (4m x 2n), warp tile 32x64.
// ---------------------------------------------------------------------------
#define BM 128
#define BN 128
#define BK 32
#define ROWB 80                      // 64B data + 16B pad per row
#define TILE_SB (128 * ROWB)         // 10240 bytes per matrix stage
#define NCHUNK (IDIM / BK)           // 8

#define LDSM_X4(r0, r1, r2, r3, addr) \
    asm volatile("ldmatrix.sync.aligned.m8n8.x4.shared.b16 {%0,%1,%2,%3}, [%4];" \
                 : "=r"(r0), "=r"(r1), "=r"(r2), "=r"(r3) : "r"(addr))

#define MMA_F16(c, a, b0, b1) \
    asm volatile("mma.sync.aligned.m16n8k16.row.col.f32.f16.f16.f32 " \
                 "{%0,%1,%2,%3}, {%4,%5,%6,%7}, {%8,%9}, {%0,%1,%2,%3};" \
                 : "+f"((c)[0]), "+f"((c)[1]), "+f"((c)[2]), "+f"((c)[3]) \
                 : "r"((a)[0]), "r"((a)[1]), "r"((a)[2]), "r"((a)[3]), \
                   "r"(b0), "r"(b1))

#define CP_ASYNC16(dst, src) \
    asm volatile("cp.async.cg.shared.global [%0], [%1], 16;" \
                 :: "r"(dst), "l"(src) : "memory")
#define CP_COMMIT() asm volatile("cp.async.commit_group;" ::: "memory")
#define CP_WAIT1()  asm volatile("cp.async.wait_group 1;" ::: "memory")
#define CP_WAIT0()  asm volatile("cp.async.wait_group 0;" ::: "memory")

__global__ __launch_bounds__(256, 1)
void indgru_gemm_hmma(const __half* __restrict__ bias_dummy,
                      const float* __restrict__ bias)
{
    __shared__ __align__(16) char sA[2 * TILE_SB];
    __shared__ __align__(16) char sB[2 * TILE_SB];

    const int tid    = threadIdx.x;
    const int lane   = tid & 31;
    const int wid    = tid >> 5;
    const int warp_m = wid & 3;      // 32-row band
    const int warp_n = wid >> 2;     // 64-col band
    const int bm = blockIdx.y * BM;
    const int bn = blockIdx.x * BN;

    const uint32_t uA = smem_u32(sA);
    const uint32_t uB = smem_u32(sB);

    // cp.async mapping: chunk c in [0,512): row = c>>2, seg = c&3 (16B each)
    const int r0 = (tid + 0)   >> 2, s0 = (tid + 0)   & 3;
    const int r1 = (tid + 256) >> 2, s1 = (tid + 256) & 3;

    const __half* gA = g_xh + (size_t)bm * IDIM;
    const __half* gB = g_wh + (size_t)bn * IDIM;

    auto issue = [&](int c) {
        const int buf = c & 1;
        const size_t ko = (size_t)(c * BK);       // halves
        CP_ASYNC16(uA + buf * TILE_SB + r0 * ROWB + s0 * 16,
                   gA + (size_t)r0 * IDIM + ko + s0 * 8);
        CP_ASYNC16(uA + buf * TILE_SB + r1 * ROWB + s1 * 16,
                   gA + (size_t)r1 * IDIM + ko + s1 * 8);
        CP_ASYNC16(uB + buf * TILE_SB + r0 * ROWB + s0 * 16,
                   gB + (size_t)r0 * IDIM + ko + s0 * 8);
        CP_ASYNC16(uB + buf * TILE_SB + r1 * ROWB + s1 * 16,
                   gB + (size_t)r1 * IDIM + ko + s1 * 8);
    };

    // ldmatrix lane addressing (mapping validated R3-R5)
    const uint32_t a_row  = warp_m * 32 + (lane & 15);
    const uint32_t a_koff = (lane >> 4) * 8;
    const uint32_t b_rowc = warp_n * 64 + ((lane >> 4) & 1) * 8 + (lane & 7);
    const uint32_t b_koff = ((lane >> 3) & 1) * 8;

    float c[2][8][4];
    #pragma unroll
    for (int mt = 0; mt < 2; ++mt)
        #pragma unroll
        for (int nt = 0; nt < 8; ++nt)
            #pragma unroll
            for (int q = 0; q < 4; ++q)
                c[mt][nt][q] = 0.0f;

    issue(0); CP_COMMIT();

    for (int ck = 0; ck < NCHUNK; ++ck) {
        if (ck + 1 < NCHUNK) {
            issue(ck + 1); CP_COMMIT();
            CP_WAIT1();
        } else {
            CP_WAIT0();
        }
        __syncthreads();

        const uint32_t bufA = uA + (ck & 1) * TILE_SB;
        const uint32_t bufB = uB + (ck & 1) * TILE_SB;

        #pragma unroll
        for (int ks = 0; ks < 2; ++ks) {
            const uint32_t kh = ks * 16;
            uint32_t a[2][4];
            #pragma unroll
            for (int mt = 0; mt < 2; ++mt)
                LDSM_X4(a[mt][0], a[mt][1], a[mt][2], a[mt][3],
                        bufA + (a_row + mt * 16) * ROWB + (kh + a_koff) * 2);
            uint32_t b[4][4];
            #pragma unroll
            for (int j = 0; j < 4; ++j)
                LDSM_X4(b[j][0], b[j][1], b[j][2], b[j][3],
                        bufB + (b_rowc + j * 16) * ROWB + (kh + b_koff) * 2);
            #pragma unroll
            for (int mt = 0; mt < 2; ++mt)
                #pragma unroll
                for (int j = 0; j < 4; ++j) {
                    MMA_F16(c[mt][2*j+0], a[mt], b[j][0], b[j][1]);
                    MMA_F16(c[mt][2*j+1], a[mt], b[j][2], b[j][3]);
                }
        }
        __syncthreads();
    }

    // Epilogue: add bias, store fp16 to g_gxh
    #pragma unroll
    for (int mt = 0; mt < 2; ++mt) {
        const int row0 = bm + warp_m * 32 + mt * 16 + (lane >> 2);
        #pragma unroll
        for (int nt = 0; nt < 8; ++nt) {
            const int n0 = bn + warp_n * 64 + nt * 8 + (lane & 3) * 2;
            const float bv0 = bias[n0];
            const float bv1 = bias[n0 + 1];
            const uint32_t h01 = pack_h2(c[mt][nt][0] + bv0, c[mt][nt][1] + bv1);
            const uint32_t h23 = pack_h2(c[mt][nt][2] + bv0, c[mt][nt][3] + bv1);
            *reinterpret_cast<uint32_t*>(g_gxh + (size_t)row0 * G3 + n0) = h01;
            *reinterpret_cast<uint32_t*>(g_gxh + (size_t)(row0 + 8) * G3 + n0) = h23;
        }
    }
}

// ---------------------------------------------------------------------------
// Scan: cp.async 4-stage ring over fp16 gx. 128 blocks x 128 threads.
// ---------------------------------------------------------------------------
__device__ __forceinline__ float tanh_fast(float x) {
    float y;
    asm("tanh.approx.f32 %0, %1;" : "=f"(y) : "f"(x));
    return y;
}

#define SB_STEPS 16
#define NSTAGE 4
#define STAGE_HALVES (SB_STEPS * 3 * 128)           // 6144
#define STAGE_BYTES  (STAGE_HALVES * 2)             // 12288
#define SCAN_SMEM    (NSTAGE * STAGE_BYTES)         // 49152
#define NT (T_LEN / SB_STEPS)                       // 128

#define CP_WAIT2() asm volatile("cp.async.wait_group 2;" ::: "memory")

__global__ __launch_bounds__(128, 1)
void indgru_scan_kernel(const float* __restrict__ b_hh,
                        const float* __restrict__ w_hh,
                        float* __restrict__ out)
{
    extern __shared__ __half shuf[];   // [NSTAGE][SB_STEPS][3][128] halves
    const uint32_t sb = smem_u32(shuf);

    const int tid  = threadIdx.x;     // 0..127
    const int bid  = blockIdx.x;      // 0..127
    const int b  = bid >> 1;
    const int h0 = (bid & 1) << 7;
    const size_t GXS = (size_t)BATCH * G3;    // 49152 halves per t
    const size_t OS  = (size_t)BATCH * HDIM;

    const __half* gbase = g_gxh + (size_t)b * G3 + h0;

    // one stage = 48 rows (16 steps x 3 gates) x 256B = 768 x 16B chunks,
    // 6 chunks per thread
    auto issue_stage = [&](int s, int buf) {
        #pragma unroll
        for (int j = 0; j < 6; ++j) {
            const int cch = tid + j * 128;       // 0..767
            const int r = cch >> 4;              // row = u*3+g
            const int q = cch & 15;              // 16B chunk within row
            const int u = r / 3, g = r % 3;
            CP_ASYNC16(sb + (uint32_t)buf * STAGE_BYTES + r * 256 + q * 16,
                       gbase + (size_t)(s * SB_STEPS + u) * GXS + g * HDIM + q * 8);
        }
    };

    issue_stage(0, 0); CP_COMMIT();
    issue_stage(1, 1); CP_COMMIT();
    issue_stage(2, 2); CP_COMMIT();

    const int i = tid;
    const int h = h0 + i;
    const float whr_h = 0.5f * w_hh[h];
    const float whz_h = 0.5f * w_hh[HDIM + h];
    const float w_hn  = w_hh[2 * HDIM + h];
    const float bhr_h = 0.5f * b_hh[h];
    const float bhz_h = 0.5f * b_hh[HDIM + h];
    const float b_hn  = b_hh[2 * HDIM + h];

    float* po = out + (size_t)b * HDIM + h;
    float hv = 0.0f;

    #pragma unroll 1
    for (int s = 0; s < NT; ++s) {
        CP_WAIT2();
        __syncthreads();

        if (s + 3 < NT) issue_stage(s + 3, (s + 3) & (NSTAGE - 1));
        CP_COMMIT();

        const __half* st = shuf + (size_t)(s & (NSTAGE - 1)) * STAGE_HALVES;
        #pragma unroll
        for (int u = 0; u < SB_STEPS; ++u) {
            const float xr = __half2float(st[(u * 3 + 0) * 128 + i]);
            const float xz = __half2float(st[(u * 3 + 1) * 128 + i]);
            const float xn = __half2float(st[(u * 3 + 2) * 128 + i]);
            const float pr = fmaf(0.5f, xr, bhr_h);
            const float pz = fmaf(0.5f, xz, bhz_h);
            const float kk = fmaf(w_hn, hv, b_hn);
            const float r = fmaf(tanh_fast(fmaf(whr_h, hv, pr)), 0.5f, 0.5f);
            const float z = fmaf(tanh_fast(fmaf(whz_h, hv, pz)), 0.5f, 0.5f);
            const float n = tanh_fast(fmaf(r, kk, xn));
            hv = fmaf(z, hv - n, n);
            po[(size_t)(s * SB_STEPS + u) * OS] = hv;
        }
    }
    out[(size_t)T_LEN * OS + (size_t)b * HDIM + h] = hv;
}

// ---------------------------------------------------------------------------
// Launch
// ---------------------------------------------------------------------------
extern "C" void kernel_launch(void* const* d_in, const int* in_sizes, int n_in,
                              void* d_out, int out_size)
{
    const float* x    = (const float*)d_in[0];   // [T, B, I]
    const float* W_ih = (const float*)d_in[1];   // [3H, I]
    const float* b_ih = (const float*)d_in[2];   // [3H]
    const float* b_hh = (const float*)d_in[3];   // [3H]
    const float* w_hh = (const float*)d_in[4];   // [3, H]
    float* out = (float*)d_out;

    static bool attr_done = false;
    if (!attr_done) {
        cudaFuncSetAttribute(indgru_scan_kernel,
                             cudaFuncAttributeMaxDynamicSharedMemorySize, SCAN_SMEM);
        attr_done = true;
    }

    convert_kernel<<<2048, 256>>>(x, W_ih);

    dim3 gemm_grid(G3 / BN, M_TOT / BM);         // (6, 1024)
    indgru_gemm_hmma<<<gemm_grid, 256>>>(nullptr, b_ih);

    indgru_scan_kernel<<<128, 128, SCAN_SMEM>>>(b_hh, w_hh, out);
}

// round 7
// speedup vs baseline: 4.7890x; 1.1462x over previous
#include <cuda_runtime.h>
#include <cuda_fp16.h>
#include <cstdint>

// Problem constants
#define T_LEN 2048
#define BATCH 64
#define IDIM  256
#define HDIM  256
#define G3    (3 * HDIM)            // 768
#define M_TOT (T_LEN * BATCH)       // 131072

// Scratch: fp16 x, fp16 W, fp16 gx
__device__ __half g_xh[(size_t)M_TOT * IDIM];     // 67 MB
__device__ __half g_wh[(size_t)G3 * IDIM];        // 393 KB
__device__ __half g_gxh[(size_t)M_TOT * G3];      // 201 MB

__device__ __forceinline__ uint32_t smem_u32(const void* p) {
    uint32_t a;
    asm("{ .reg .u64 t; cvta.to.shared.u64 t, %1; cvt.u32.u64 %0, t; }" : "=r"(a) : "l"(p));
    return a;
}

__device__ __forceinline__ uint32_t pack_h2(float x, float y) {
    __half2 t = __floats2half2_rn(x, y);
    return *reinterpret_cast<uint32_t*>(&t);
}

// ---------------------------------------------------------------------------
// Convert: x (and W) fp32 -> fp16 scratch.  Grid-stride over float4 units.
// ---------------------------------------------------------------------------
#define XN4 ((size_t)M_TOT * IDIM / 4)
#define WN4 ((size_t)G3 * IDIM / 4)

__global__ __launch_bounds__(256)
void convert_kernel(const float* __restrict__ x, const float* __restrict__ W)
{
    const size_t total = XN4 + WN4;
    for (size_t i = (size_t)blockIdx.x * blockDim.x + threadIdx.x;
         i < total; i += (size_t)gridDim.x * blockDim.x) {
        if (i < XN4) {
            float4 v = reinterpret_cast<const float4*>(x)[i];
            reinterpret_cast<uint2*>(g_xh)[i] =
                make_uint2(pack_h2(v.x, v.y), pack_h2(v.z, v.w));
        } else {
            const size_t j = i - XN4;
            float4 v = reinterpret_cast<const float4*>(W)[j];
            reinterpret_cast<uint2*>(g_wh)[j] =
                make_uint2(pack_h2(v.x, v.y), pack_h2(v.z, v.w));
        }
    }
}

// ---------------------------------------------------------------------------
// HMMA fp16 GEMM, 3-stage cp.async ring: gxh = xh @ Wh^T + bias (fp16 out)
// CTA tile 128(M) x 128(N) x 32(K). 8 warps (4m x 2n), warp tile 32x64.
// One __syncthreads per k-chunk; 2 CTAs/SM.
// ---------------------------------------------------------------------------
#define BM 128
#define BN 128
#define BK 32
#define ROWB 80                      // 64B data + 16B pad per row
#define TILE_SB (128 * ROWB)         // 10240 bytes per matrix stage
#define NCHUNK (IDIM / BK)           // 8
#define NSTG 3
#define GEMM_SMEM (NSTG * 2 * TILE_SB)   // 61440

#define LDSM_X4(r0, r1, r2, r3, addr) \
    asm volatile("ldmatrix.sync.aligned.m8n8.x4.shared.b16 {%0,%1,%2,%3}, [%4];" \
                 : "=r"(r0), "=r"(r1), "=r"(r2), "=r"(r3) : "r"(addr))

#define MMA_F16(c, a, b0, b1) \
    asm volatile("mma.sync.aligned.m16n8k16.row.col.f32.f16.f16.f32 " \
                 "{%0,%1,%2,%3}, {%4,%5,%6,%7}, {%8,%9}, {%0,%1,%2,%3};" \
                 : "+f"((c)[0]), "+f"((c)[1]), "+f"((c)[2]), "+f"((c)[3]) \
                 : "r"((a)[0]), "r"((a)[1]), "r"((a)[2]), "r"((a)[3]), \
                   "r"(b0), "r"(b1))

#define CP_ASYNC16(dst, src) \
    asm volatile("cp.async.cg.shared.global [%0], [%1], 16;" \
                 :: "r"(dst), "l"(src) : "memory")
#define CP_COMMIT() asm volatile("cp.async.commit_group;" ::: "memory")
#define CP_WAIT1()  asm volatile("cp.async.wait_group 1;" ::: "memory")

__global__ __launch_bounds__(256, 2)
void indgru_gemm_hmma(const float* __restrict__ bias)
{
    extern __shared__ __align__(16) char gsm[];
    // layout: [NSTG][A: TILE_SB | B: TILE_SB]
    const uint32_t uS = smem_u32(gsm);

    const int tid    = threadIdx.x;
    const int lane   = tid & 31;
    const int wid    = tid >> 5;
    const int warp_m = wid & 3;      // 32-row band
    const int warp_n = wid >> 2;     // 64-col band
    const int bm = blockIdx.y * BM;
    const int bn = blockIdx.x * BN;

    // cp.async mapping: chunk c in [0,512): row = c>>2, seg = c&3 (16B each)
    const int r0 = (tid + 0)   >> 2, s0 = (tid + 0)   & 3;
    const int r1 = (tid + 256) >> 2, s1 = (tid + 256) & 3;

    const __half* gA = g_xh + (size_t)bm * IDIM;
    const __half* gB = g_wh + (size_t)bn * IDIM;

    auto issue = [&](int c) {
        if (c < NCHUNK) {
            const uint32_t buf = uS + (uint32_t)(c % NSTG) * (2 * TILE_SB);
            const size_t ko = (size_t)(c * BK);       // halves
            CP_ASYNC16(buf + r0 * ROWB + s0 * 16,
                       gA + (size_t)r0 * IDIM + ko + s0 * 8);
            CP_ASYNC16(buf + r1 * ROWB + s1 * 16,
                       gA + (size_t)r1 * IDIM + ko + s1 * 8);
            CP_ASYNC16(buf + TILE_SB + r0 * ROWB + s0 * 16,
                       gB + (size_t)r0 * IDIM + ko + s0 * 8);
            CP_ASYNC16(buf + TILE_SB + r1 * ROWB + s1 * 16,
                       gB + (size_t)r1 * IDIM + ko + s1 * 8);
        }
        CP_COMMIT();
    };

    // ldmatrix lane addressing (mapping validated R3-R6)
    const uint32_t a_row  = warp_m * 32 + (lane & 15);
    const uint32_t a_koff = (lane >> 4) * 8;
    const uint32_t b_rowc = warp_n * 64 + ((lane >> 4) & 1) * 8 + (lane & 7);
    const uint32_t b_koff = ((lane >> 3) & 1) * 8;

    float c[2][8][4];
    #pragma unroll
    for (int mt = 0; mt < 2; ++mt)
        #pragma unroll
        for (int nt = 0; nt < 8; ++nt)
            #pragma unroll
            for (int q = 0; q < 4; ++q)
                c[mt][nt][q] = 0.0f;

    issue(0);
    issue(1);

    #pragma unroll 1
    for (int ck = 0; ck < NCHUNK; ++ck) {
        CP_WAIT1();              // stage ck resident
        __syncthreads();         // all consumed stage ck-1; safe to refill ck+2
        issue(ck + 2);

        const uint32_t bufA = uS + (uint32_t)(ck % NSTG) * (2 * TILE_SB);
        const uint32_t bufB = bufA + TILE_SB;

        #pragma unroll
        for (int ks = 0; ks < 2; ++ks) {
            const uint32_t kh = ks * 16;
            uint32_t a[2][4];
            #pragma unroll
            for (int mt = 0; mt < 2; ++mt)
                LDSM_X4(a[mt][0], a[mt][1], a[mt][2], a[mt][3],
                        bufA + (a_row + mt * 16) * ROWB + (kh + a_koff) * 2);
            uint32_t b[4][4];
            #pragma unroll
            for (int j = 0; j < 4; ++j)
                LDSM_X4(b[j][0], b[j][1], b[j][2], b[j][3],
                        bufB + (b_rowc + j * 16) * ROWB + (kh + b_koff) * 2);
            #pragma unroll
            for (int mt = 0; mt < 2; ++mt)
                #pragma unroll
                for (int j = 0; j < 4; ++j) {
                    MMA_F16(c[mt][2*j+0], a[mt], b[j][0], b[j][1]);
                    MMA_F16(c[mt][2*j+1], a[mt], b[j][2], b[j][3]);
                }
        }
    }

    // Epilogue: add bias, store fp16 to g_gxh
    #pragma unroll
    for (int mt = 0; mt < 2; ++mt) {
        const int row0 = bm + warp_m * 32 + mt * 16 + (lane >> 2);
        #pragma unroll
        for (int nt = 0; nt < 8; ++nt) {
            const int n0 = bn + warp_n * 64 + nt * 8 + (lane & 3) * 2;
            const float bv0 = bias[n0];
            const float bv1 = bias[n0 + 1];
            const uint32_t h01 = pack_h2(c[mt][nt][0] + bv0, c[mt][nt][1] + bv1);
            const uint32_t h23 = pack_h2(c[mt][nt][2] + bv0, c[mt][nt][3] + bv1);
            *reinterpret_cast<uint32_t*>(g_gxh + (size_t)row0 * G3 + n0) = h01;
            *reinterpret_cast<uint32_t*>(g_gxh + (size_t)(row0 + 8) * G3 + n0) = h23;
        }
    }
}

// ---------------------------------------------------------------------------
// Scan: cp.async 4-stage ring over fp16 gx. 128 blocks x 128 threads.
// ---------------------------------------------------------------------------
__device__ __forceinline__ float tanh_fast(float x) {
    float y;
    asm("tanh.approx.f32 %0, %1;" : "=f"(y) : "f"(x));
    return y;
}

#define SB_STEPS 16
#define NSTAGE 4
#define STAGE_HALVES (SB_STEPS * 3 * 128)           // 6144
#define STAGE_BYTES  (STAGE_HALVES * 2)             // 12288
#define SCAN_SMEM    (NSTAGE * STAGE_BYTES)         // 49152
#define NT (T_LEN / SB_STEPS)                       // 128

#define CP_WAIT2() asm volatile("cp.async.wait_group 2;" ::: "memory")

__global__ __launch_bounds__(128, 1)
void indgru_scan_kernel(const float* __restrict__ b_hh,
                        const float* __restrict__ w_hh,
                        float* __restrict__ out)
{
    extern __shared__ __half shuf[];   // [NSTAGE][SB_STEPS][3][128] halves
    const uint32_t sb = smem_u32(shuf);

    const int tid  = threadIdx.x;     // 0..127
    const int bid  = blockIdx.x;      // 0..127
    const int b  = bid >> 1;
    const int h0 = (bid & 1) << 7;
    const size_t GXS = (size_t)BATCH * G3;    // 49152 halves per t
    const size_t OS  = (size_t)BATCH * HDIM;

    const __half* gbase = g_gxh + (size_t)b * G3 + h0;

    auto issue_stage = [&](int s, int buf) {
        #pragma unroll
        for (int j = 0; j < 6; ++j) {
            const int cch = tid + j * 128;       // 0..767
            const int r = cch >> 4;              // row = u*3+g
            const int q = cch & 15;              // 16B chunk within row
            const int u = r / 3, g = r % 3;
            CP_ASYNC16(sb + (uint32_t)buf * STAGE_BYTES + r * 256 + q * 16,
                       gbase + (size_t)(s * SB_STEPS + u) * GXS + g * HDIM + q * 8);
        }
    };

    issue_stage(0, 0); CP_COMMIT();
    issue_stage(1, 1); CP_COMMIT();
    issue_stage(2, 2); CP_COMMIT();

    const int i = tid;
    const int h = h0 + i;
    const float whr_h = 0.5f * w_hh[h];
    const float whz_h = 0.5f * w_hh[HDIM + h];
    const float w_hn  = w_hh[2 * HDIM + h];
    const float bhr_h = 0.5f * b_hh[h];
    const float bhz_h = 0.5f * b_hh[HDIM + h];
    const float b_hn  = b_hh[2 * HDIM + h];

    float* po = out + (size_t)b * HDIM + h;
    float hv = 0.0f;

    #pragma unroll 1
    for (int s = 0; s < NT; ++s) {
        CP_WAIT2();
        __syncthreads();

        if (s + 3 < NT) issue_stage(s + 3, (s + 3) & (NSTAGE - 1));
        CP_COMMIT();

        const __half* st = shuf + (size_t)(s & (NSTAGE - 1)) * STAGE_HALVES;
        #pragma unroll
        for (int u = 0; u < SB_STEPS; ++u) {
            const float xr = __half2float(st[(u * 3 + 0) * 128 + i]);
            const float xz = __half2float(st[(u * 3 + 1) * 128 + i]);
            const float xn = __half2float(st[(u * 3 + 2) * 128 + i]);
            const float pr = fmaf(0.5f, xr, bhr_h);
            const float pz = fmaf(0.5f, xz, bhz_h);
            const float kk = fmaf(w_hn, hv, b_hn);
            const float r = fmaf(tanh_fast(fmaf(whr_h, hv, pr)), 0.5f, 0.5f);
            const float z = fmaf(tanh_fast(fmaf(whz_h, hv, pz)), 0.5f, 0.5f);
            const float n = tanh_fast(fmaf(r, kk, xn));
            hv = fmaf(z, hv - n, n);
            po[(size_t)(s * SB_STEPS + u) * OS] = hv;
        }
    }
    out[(size_t)T_LEN * OS + (size_t)b * HDIM + h] = hv;
}

// ---------------------------------------------------------------------------
// Launch
// ---------------------------------------------------------------------------
extern "C" void kernel_launch(void* const* d_in, const int* in_sizes, int n_in,
                              void* d_out, int out_size)
{
    const float* x    = (const float*)d_in[0];   // [T, B, I]
    const float* W_ih = (const float*)d_in[1];   // [3H, I]
    const float* b_ih = (const float*)d_in[2];   // [3H]
    const float* b_hh = (const float*)d_in[3];   // [3H]
    const float* w_hh = (const float*)d_in[4];   // [3, H]
    float* out = (float*)d_out;

    static bool attr_done = false;
    if (!attr_done) {
        cudaFuncSetAttribute(indgru_gemm_hmma,
                             cudaFuncAttributeMaxDynamicSharedMemorySize, GEMM_SMEM);
        cudaFuncSetAttribute(indgru_scan_kernel,
                             cudaFuncAttributeMaxDynamicSharedMemorySize, SCAN_SMEM);
        attr_done = true;
    }

    convert_kernel<<<2048, 256>>>(x, W_ih);

    dim3 gemm_grid(G3 / BN, M_TOT / BM);         // (6, 1024)
    indgru_gemm_hmma<<<gemm_grid, 256, GEMM_SMEM>>>(b_ih);

    indgru_scan_kernel<<<128, 128, SCAN_SMEM>>>(b_hh, w_hh, out);
}

// round 8
// speedup vs baseline: 5.7785x; 1.2066x over previous
#include <cuda_runtime.h>
#include <cuda_fp16.h>
#include <cstdint>

// Problem constants
#define T_LEN 2048
#define BATCH 64
#define IDIM  256
#define HDIM  256
#define G3    (3 * HDIM)            // 768
#define M_TOT (T_LEN * BATCH)       // 131072

// fp16 scratch for x and W
__device__ __half g_xh[(size_t)M_TOT * IDIM];     // 67 MB
__device__ __half g_wh[(size_t)G3 * IDIM];        // 393 KB

__device__ __forceinline__ uint32_t smem_u32(const void* p) {
    uint32_t a;
    asm("{ .reg .u64 t; cvta.to.shared.u64 t, %1; cvt.u32.u64 %0, t; }" : "=r"(a) : "l"(p));
    return a;
}

__device__ __forceinline__ uint32_t pack_h2(float x, float y) {
    __half2 t = __floats2half2_rn(x, y);
    return *reinterpret_cast<uint32_t*>(&t);
}

// ---------------------------------------------------------------------------
// Convert: x and W fp32 -> fp16 scratch.
// ---------------------------------------------------------------------------
#define XN4 ((size_t)M_TOT * IDIM / 4)
#define WN4 ((size_t)G3 * IDIM / 4)

__global__ __launch_bounds__(256)
void convert_kernel(const float* __restrict__ x, const float* __restrict__ W)
{
    const size_t total = XN4 + WN4;
    for (size_t i = (size_t)blockIdx.x * blockDim.x + threadIdx.x;
         i < total; i += (size_t)gridDim.x * blockDim.x) {
        if (i < XN4) {
            float4 v = reinterpret_cast<const float4*>(x)[i];
            reinterpret_cast<uint2*>(g_xh)[i] =
                make_uint2(pack_h2(v.x, v.y), pack_h2(v.z, v.w));
        } else {
            const size_t j = i - XN4;
            float4 v = reinterpret_cast<const float4*>(W)[j];
            reinterpret_cast<uint2*>(g_wh)[j] =
                make_uint2(pack_h2(v.x, v.y), pack_h2(v.z, v.w));
        }
    }
}

// ---------------------------------------------------------------------------
// Fused GEMM + scan, persistent per (batch, h-half).
// ---------------------------------------------------------------------------
#define LDSM_X4(r0, r1, r2, r3, addr) \
    asm volatile("ldmatrix.sync.aligned.m8n8.x4.shared.b16 {%0,%1,%2,%3}, [%4];" \
                 : "=r"(r0), "=r"(r1), "=r"(r2), "=r"(r3) : "r"(addr))

#define MMA_F16(c, a, b0, b1) \
    asm volatile("mma.sync.aligned.m16n8k16.row.col.f32.f16.f16.f32 " \
                 "{%0,%1,%2,%3}, {%4,%5,%6,%7}, {%8,%9}, {%0,%1,%2,%3};" \
                 : "+f"((c)[0]), "+f"((c)[1]), "+f"((c)[2]), "+f"((c)[3]) \
                 : "r"((a)[0]), "r"((a)[1]), "r"((a)[2]), "r"((a)[3]), \
                   "r"(b0), "r"(b1))

#define CP_ASYNC16(dst, src) \
    asm volatile("cp.async.cg.shared.global [%0], [%1], 16;" \
                 :: "r"(dst), "l"(src) : "memory")
#define CP_COMMIT() asm volatile("cp.async.commit_group;" ::: "memory")
#define CP_WAIT0()  asm volatile("cp.async.wait_group 0;" ::: "memory")

// smem layout (bytes)
#define B_OFF     0
#define B_BYTES   196608              // 384 rows x 512B, SW-swizzled
#define A_OFF     196608
#define A_BYTES   10240               // [kt(8)][row(16)][80B]
#define RING_OFF  206848
#define RING_SLOT 12288               // 16 steps x 3 gates x 128 h x fp16
#define FUSED_SMEM 231424             // + 2 ring slots

#define NCHUNKS (T_LEN / 16)          // 128

__device__ __forceinline__ float tanh_fast(float x) {
    float y;
    asm("tanh.approx.f32 %0, %1;" : "=f"(y) : "f"(x));
    return y;
}

// B smem swizzle: row j (0..383), 16B-chunk cc (0..31)
__device__ __forceinline__ uint32_t b_swz(int j, int cc) {
    return (uint32_t)(j * 512 + (((cc & 24) | ((cc ^ j) & 7)) << 4));
}

// ring byte offset for (step u, gate g, h)
__device__ __forceinline__ uint32_t ring_off(int u, int g, int h) {
    return (uint32_t)(u * 768 + g * 256 + ((h << 1) ^ ((u & 7) << 4)));
}

// Produce one 16-step chunk of this warp's N-slice into the ring slot.
template<int NT>
__device__ __forceinline__ void produce_chunk(
    uint32_t uB, char* ringslot, const uint32_t (&af)[64],
    const float (&bv0)[8], const float (&bv1)[8], int n0, int lane)
{
    float acc[NT][4];
    #pragma unroll
    for (int t = 0; t < NT; ++t) {
        acc[t][0] = acc[t][1] = acc[t][2] = acc[t][3] = 0.0f;
    }

    const int jrow = ((lane >> 4) & 1) * 8 + (lane & 7);
    const int cbit = (lane >> 3) & 1;

    #pragma unroll
    for (int kk = 0; kk < 16; ++kk) {
        const int cc = 2 * kk + cbit;
        #pragma unroll
        for (int p = 0; p < NT / 2; ++p) {
            const int j = n0 + p * 16 + jrow;
            uint32_t b0, b1, b2, b3;
            LDSM_X4(b0, b1, b2, b3, uB + b_swz(j, cc));
            MMA_F16(acc[2 * p],     af + kk * 4, b0, b1);
            MMA_F16(acc[2 * p + 1], af + kk * 4, b2, b3);
        }
    }

    // epilogue: bias add, pack fp16, store into ring
    const int u0 = lane >> 2;
    #pragma unroll
    for (int tl = 0; tl < NT; ++tl) {
        const int j = n0 + tl * 8 + (lane & 3) * 2;
        const int g = j >> 7, h = j & 127;
        *(uint32_t*)(ringslot + ring_off(u0, g, h)) =
            pack_h2(acc[tl][0] + bv0[tl], acc[tl][1] + bv1[tl]);
        *(uint32_t*)(ringslot + ring_off(u0 + 8, g, h)) =
            pack_h2(acc[tl][2] + bv0[tl], acc[tl][3] + bv1[tl]);
    }
}

__global__ void __launch_bounds__(256, 1)
indgru_fused(const float* __restrict__ bias,
             const float* __restrict__ b_hh,
             const float* __restrict__ w_hh,
             float* __restrict__ out)
{
    extern __shared__ __align__(16) char gsm[];
    const uint32_t uS = smem_u32(gsm);
    const uint32_t uB = uS + B_OFF;
    const uint32_t uA = uS + A_OFF;

    const int tid  = threadIdx.x;
    const int lane = tid & 31;
    const int wid  = tid >> 5;
    const int bid  = blockIdx.x;            // 0..127
    const int b    = bid >> 1;
    const int h0   = (bid & 1) << 7;
    const size_t OS = (size_t)BATCH * HDIM; // 16384

    // ---- load B panel (384 rows x 256 halves), swizzled ----
    #pragma unroll 4
    for (int i = 0; i < 48; ++i) {
        const int idx = tid + i * 256;       // 0..12287
        const int j = idx >> 5, cc = idx & 31;
        const int wrow = (j >> 7) * 256 + h0 + (j & 127);
        CP_ASYNC16(uB + b_swz(j, cc), g_wh + (size_t)wrow * 256 + cc * 8);
    }

    // ---- A chunk loader: 16 rows (t-steps) x 256 halves, [kt][row][80B] ----
    auto issueA = [&](int c) {
        #pragma unroll
        for (int i = 0; i < 2; ++i) {
            const int idx = tid + i * 256;   // 0..511
            const int row = idx >> 5, rem = idx & 31;
            const int kt = rem >> 2, seg = rem & 3;
            CP_ASYNC16(uA + kt * 1280 + row * 80 + seg * 16,
                       g_xh + ((size_t)((c * 16 + row) * 64 + b)) * 256
                            + kt * 32 + seg * 8);
        }
    };

    issueA(0);
    CP_COMMIT();        // B + A(0) in one group

    // ---- per-warp GEMM slice: warps 0-3 get 32 cols, warps 4-7 get 64 ----
    const int n0 = (wid < 4) ? wid * 32 : 128 + (wid - 4) * 64;
    const int nt = (wid < 4) ? 4 : 8;
    float bv0[8], bv1[8];
    #pragma unroll
    for (int tl = 0; tl < 8; ++tl) {
        if (tl < nt) {
            const int j = n0 + tl * 8 + (lane & 3) * 2;
            const int wr = (j >> 7) * 256 + h0 + (j & 127);
            bv0[tl] = bias[wr];
            bv1[tl] = bias[wr + 1];
        } else { bv0[tl] = 0.0f; bv1[tl] = 0.0f; }
    }

    // ---- scan parameters (threads 0-127 own one chain each) ----
    const int h = h0 + tid;
    float whr_h = 0.f, whz_h = 0.f, w_hn = 0.f, bhr_h = 0.f, bhz_h = 0.f, b_hn = 0.f;
    float hv = 0.0f;
    float* po = out;
    if (tid < 128) {
        whr_h = 0.5f * w_hh[h];
        whz_h = 0.5f * w_hh[HDIM + h];
        w_hn  = w_hh[2 * HDIM + h];
        bhr_h = 0.5f * b_hh[h];
        bhz_h = 0.5f * b_hh[HDIM + h];
        b_hn  = b_hh[2 * HDIM + h];
        po = out + (size_t)b * HDIM + h;
    }

    uint32_t af[64];   // A fragments for the current chunk (register-resident)
    auto loadAf = [&]() {
        #pragma unroll
        for (int kk = 0; kk < 16; ++kk) {
            LDSM_X4(af[kk * 4], af[kk * 4 + 1], af[kk * 4 + 2], af[kk * 4 + 3],
                    uA + (kk >> 1) * 1280 + (lane & 15) * 80
                       + (((kk & 1) * 16 + (lane >> 4) * 8) << 1));
        }
    };

    // ---- main loop: produce chunk c, scan chunk c-1 ----
    #pragma unroll 1
    for (int c = 0; c <= NCHUNKS; ++c) {
        if (c < NCHUNKS) {
            CP_WAIT0();              // A(c) resident (and B on c==0)
            __syncthreads();         // ring[c&1] free; prev epilogue visible
            loadAf();
            __syncthreads();         // all warps consumed A buffer
            if (c + 1 < NCHUNKS) issueA(c + 1);
            CP_COMMIT();
            char* ringslot = gsm + RING_OFF + (c & 1) * RING_SLOT;
            if (wid < 4)
                produce_chunk<4>(uB, ringslot, af, bv0, bv1, n0, lane);
            else
                produce_chunk<8>(uB, ringslot, af, bv0, bv1, n0, lane);
        } else {
            __syncthreads();         // make last epilogue visible
        }

        if (c >= 1 && tid < 128) {
            const int s = c - 1;
            const char* st = gsm + RING_OFF + (s & 1) * RING_SLOT;
            const int i = tid;
            #pragma unroll
            for (int u = 0; u < 16; ++u) {
                const uint32_t sw = (uint32_t)((i << 1) ^ ((u & 7) << 4));
                const float xr = __half2float(*(const __half*)(st + u * 768 +   0 + sw));
                const float xz = __half2float(*(const __half*)(st + u * 768 + 256 + sw));
                const float xn = __half2float(*(const __half*)(st + u * 768 + 512 + sw));
                const float pr = fmaf(0.5f, xr, bhr_h);
                const float pz = fmaf(0.5f, xz, bhz_h);
                const float kk = fmaf(w_hn, hv, b_hn);
                const float r = fmaf(tanh_fast(fmaf(whr_h, hv, pr)), 0.5f, 0.5f);
                const float z = fmaf(tanh_fast(fmaf(whz_h, hv, pz)), 0.5f, 0.5f);
                const float n = tanh_fast(fmaf(r, kk, xn));
                hv = fmaf(z, hv - n, n);
                po[(size_t)(s * 16 + u) * OS] = hv;
            }
        }
    }

    if (tid < 128)
        out[(size_t)T_LEN * OS + (size_t)b * HDIM + h] = hv;
}

// ---------------------------------------------------------------------------
// Launch
// ---------------------------------------------------------------------------
extern "C" void kernel_launch(void* const* d_in, const int* in_sizes, int n_in,
                              void* d_out, int out_size)
{
    const float* x    = (const float*)d_in[0];   // [T, B, I]
    const float* W_ih = (const float*)d_in[1];   // [3H, I]
    const float* b_ih = (const float*)d_in[2];   // [3H]
    const float* b_hh = (const float*)d_in[3];   // [3H]
    const float* w_hh = (const float*)d_in[4];   // [3, H]
    float* out = (float*)d_out;

    static bool attr_done = false;
    if (!attr_done) {
        cudaFuncSetAttribute(indgru_fused,
                             cudaFuncAttributeMaxDynamicSharedMemorySize, FUSED_SMEM);
        attr_done = true;
    }

    convert_kernel<<<2048, 256>>>(x, W_ih);
    indgru_fused<<<128, 256, FUSED_SMEM>>>(b_ih, b_hh, w_hh, out);
}

// round 9
// speedup vs baseline: 7.3617x; 1.2740x over previous
#include <cuda_runtime.h>
#include <cuda_fp16.h>
#include <cstdint>

// Problem constants
#define T_LEN 2048
#define BATCH 64
#define IDIM  256
#define HDIM  256
#define G3    (3 * HDIM)            // 768
#define M_TOT (T_LEN * BATCH)       // 131072

// fp16 scratch for x and W
__device__ __half g_xh[(size_t)M_TOT * IDIM];     // 67 MB
__device__ __half g_wh[(size_t)G3 * IDIM];        // 393 KB

__device__ __forceinline__ uint32_t smem_u32(const void* p) {
    uint32_t a;
    asm("{ .reg .u64 t; cvta.to.shared.u64 t, %1; cvt.u32.u64 %0, t; }" : "=r"(a) : "l"(p));
    return a;
}

__device__ __forceinline__ uint32_t pack_h2(float x, float y) {
    __half2 t = __floats2half2_rn(x, y);
    return *reinterpret_cast<uint32_t*>(&t);
}

// ---------------------------------------------------------------------------
// Convert: x and W fp32 -> fp16 scratch.
// ---------------------------------------------------------------------------
#define XN4 ((size_t)M_TOT * IDIM / 4)
#define WN4 ((size_t)G3 * IDIM / 4)

__global__ __launch_bounds__(256)
void convert_kernel(const float* __restrict__ x, const float* __restrict__ W)
{
    const size_t total = XN4 + WN4;
    for (size_t i = (size_t)blockIdx.x * blockDim.x + threadIdx.x;
         i < total; i += (size_t)gridDim.x * blockDim.x) {
        if (i < XN4) {
            float4 v = reinterpret_cast<const float4*>(x)[i];
            reinterpret_cast<uint2*>(g_xh)[i] =
                make_uint2(pack_h2(v.x, v.y), pack_h2(v.z, v.w));
        } else {
            const size_t j = i - XN4;
            float4 v = reinterpret_cast<const float4*>(W)[j];
            reinterpret_cast<uint2*>(g_wh)[j] =
                make_uint2(pack_h2(v.x, v.y), pack_h2(v.z, v.w));
        }
    }
}

// ---------------------------------------------------------------------------
// Fused GEMM + scan, warp-specialized: warps 4-7 produce, warps 0-3 scan.
// ---------------------------------------------------------------------------
#define LDSM_X4(r0, r1, r2, r3, addr) \
    asm volatile("ldmatrix.sync.aligned.m8n8.x4.shared.b16 {%0,%1,%2,%3}, [%4];" \
                 : "=r"(r0), "=r"(r1), "=r"(r2), "=r"(r3) : "r"(addr))

#define MMA_F16(c, a, b0, b1) \
    asm volatile("mma.sync.aligned.m16n8k16.row.col.f32.f16.f16.f32 " \
                 "{%0,%1,%2,%3}, {%4,%5,%6,%7}, {%8,%9}, {%0,%1,%2,%3};" \
                 : "+f"((c)[0]), "+f"((c)[1]), "+f"((c)[2]), "+f"((c)[3]) \
                 : "r"((a)[0]), "r"((a)[1]), "r"((a)[2]), "r"((a)[3]), \
                   "r"(b0), "r"(b1))

#define CP_ASYNC16(dst, src) \
    asm volatile("cp.async.cg.shared.global [%0], [%1], 16;" \
                 :: "r"(dst), "l"(src) : "memory")
#define CP_COMMIT() asm volatile("cp.async.commit_group;" ::: "memory")
#define CP_WAIT0()  asm volatile("cp.async.wait_group 0;" ::: "memory")

#define BAR_SYNC(id, cnt) \
    asm volatile("bar.sync %0, %1;" :: "r"(id), "r"(cnt) : "memory")
#define BAR_ARRIVE(id, cnt) \
    asm volatile("bar.arrive %0, %1;" :: "r"(id), "r"(cnt) : "memory")

// Barrier ids: 1,2 = ring slot free; 3,4 = ring slot full; 5 = producer A buf
// smem layout (bytes)
#define B_OFF     0
#define B_BYTES   196608              // 384 rows x 512B, swizzled
#define A_OFF     196608
#define A_BYTES   10240               // [kt(8)][row(16)][80B]
#define RING_OFF  206848
#define RING_SLOT 12288               // 16 steps x 3 gates x 128 h x fp16
#define FUSED_SMEM 231424

#define NCHUNKS (T_LEN / 16)          // 128

__device__ __forceinline__ float tanh_fast(float x) {
    float y;
    asm("tanh.approx.f32 %0, %1;" : "=f"(y) : "f"(x));
    return y;
}

// B smem swizzle: row j (0..383), 16B-chunk cc (0..31)
__device__ __forceinline__ uint32_t b_swz(int j, int cc) {
    return (uint32_t)(j * 512 + (((cc & 24) | ((cc ^ j) & 7)) << 4));
}

// ring byte offset for (step u, gate g, h)
__device__ __forceinline__ uint32_t ring_off(int u, int g, int h) {
    return (uint32_t)(u * 768 + g * 256 + ((h << 1) ^ ((u & 7) << 4)));
}

__global__ void __launch_bounds__(256, 1)
indgru_fused(const float* __restrict__ bias,
             const float* __restrict__ b_hh,
             const float* __restrict__ w_hh,
             float* __restrict__ out)
{
    extern __shared__ __align__(16) char gsm[];
    const uint32_t uS = smem_u32(gsm);
    const uint32_t uB = uS + B_OFF;
    const uint32_t uA = uS + A_OFF;

    const int tid  = threadIdx.x;
    const int lane = tid & 31;
    const int wid  = tid >> 5;
    const int bid  = blockIdx.x;            // 0..127
    const int b    = bid >> 1;
    const int h0   = (bid & 1) << 7;
    const size_t OS = (size_t)BATCH * HDIM; // 16384

    // ---- prologue: all threads load B panel; producers load A(0) ----
    #pragma unroll 4
    for (int i = 0; i < 48; ++i) {
        const int idx = tid + i * 256;       // 0..12287
        const int j = idx >> 5, cc = idx & 31;
        const int wrow = (j >> 7) * 256 + h0 + (j & 127);
        CP_ASYNC16(uB + b_swz(j, cc), g_wh + (size_t)wrow * 256 + cc * 8);
    }

    // producer-only A loader (128 threads, 4x16B each)
    auto issueA = [&](int c) {
        if (c < NCHUNKS) {
            const int pt = tid - 128;
            #pragma unroll
            for (int i = 0; i < 4; ++i) {
                const int idx = pt + i * 128;    // 0..511
                const int row = idx >> 5, rem = idx & 31;
                const int kt = rem >> 2, seg = rem & 3;
                CP_ASYNC16(uA + kt * 1280 + row * 80 + seg * 16,
                           g_xh + ((size_t)((c * 16 + row) * 64 + b)) * 256
                                + kt * 32 + seg * 8);
            }
        }
        CP_COMMIT();
    };

    if (tid >= 128) issueA(0); else CP_COMMIT();
    CP_WAIT0();
    __syncthreads();      // B + A(0) visible to everyone

    if (tid >= 128) {
        // =========================== PRODUCERS ===========================
        const int pw = wid - 4;              // 0..3
        const int n0 = pw * 96;

        float bv0[12], bv1[12];
        #pragma unroll
        for (int tl = 0; tl < 12; ++tl) {
            const int j = n0 + tl * 8 + (lane & 3) * 2;
            const int wr = (j >> 7) * 256 + h0 + (j & 127);
            bv0[tl] = bias[wr];
            bv1[tl] = bias[wr + 1];
        }

        const int jrow = ((lane >> 4) & 1) * 8 + (lane & 7);
        const int cbit = (lane >> 3) & 1;
        const int u0 = lane >> 2;

        uint32_t af[64];

        #pragma unroll 1
        for (int c = 0; c < NCHUNKS; ++c) {
            CP_WAIT0();                // this thread's A(c) copies done
            BAR_SYNC(5, 128);          // all producers' copies done -> visible
            #pragma unroll
            for (int kk = 0; kk < 16; ++kk) {
                LDSM_X4(af[kk*4], af[kk*4+1], af[kk*4+2], af[kk*4+3],
                        uA + (kk >> 1) * 1280 + (lane & 15) * 80
                           + (((kk & 1) * 16 + (lane >> 4) * 8) << 1));
            }
            BAR_SYNC(5, 128);          // A buffer consumed by all producers
            issueA(c + 1);             // refill during MMAs

            float acc[12][4];
            #pragma unroll
            for (int t = 0; t < 12; ++t)
                acc[t][0] = acc[t][1] = acc[t][2] = acc[t][3] = 0.0f;

            #pragma unroll
            for (int kk = 0; kk < 16; ++kk) {
                const int cc = 2 * kk + cbit;
                #pragma unroll
                for (int p = 0; p < 6; ++p) {
                    const int j = n0 + p * 16 + jrow;
                    uint32_t r0, r1, r2, r3;
                    LDSM_X4(r0, r1, r2, r3, uB + b_swz(j, cc));
                    MMA_F16(acc[2*p],   af + kk*4, r0, r1);
                    MMA_F16(acc[2*p+1], af + kk*4, r2, r3);
                }
            }

            BAR_SYNC(1 + (c & 1), 256);      // ring slot free (consumers done c-2)
            char* ringslot = gsm + RING_OFF + (c & 1) * RING_SLOT;
            #pragma unroll
            for (int tl = 0; tl < 12; ++tl) {
                const int j = n0 + tl * 8 + (lane & 3) * 2;
                const int g = j >> 7, h = j & 127;
                *(uint32_t*)(ringslot + ring_off(u0, g, h)) =
                    pack_h2(acc[tl][0] + bv0[tl], acc[tl][1] + bv1[tl]);
                *(uint32_t*)(ringslot + ring_off(u0 + 8, g, h)) =
                    pack_h2(acc[tl][2] + bv0[tl], acc[tl][3] + bv1[tl]);
            }
            BAR_ARRIVE(3 + (c & 1), 256);    // slot full
        }
    } else {
        // =========================== CONSUMERS ===========================
        const int i = tid;                   // 0..127
        const int h = h0 + i;
        const float whr_h = 0.5f * w_hh[h];
        const float whz_h = 0.5f * w_hh[HDIM + h];
        const float w_hn  = w_hh[2 * HDIM + h];
        const float bhr_h = 0.5f * b_hh[h];
        const float bhz_h = 0.5f * b_hh[HDIM + h];
        const float b_hn  = b_hh[2 * HDIM + h];
        float* po = out + (size_t)b * HDIM + h;
        float hv = 0.0f;

        BAR_ARRIVE(1, 256);                  // pre-arm slot 0 free
        BAR_ARRIVE(2, 256);                  // pre-arm slot 1 free

        #pragma unroll 1
        for (int s = 0; s < NCHUNKS; ++s) {
            BAR_SYNC(3 + (s & 1), 256);      // slot full
            const char* st = gsm + RING_OFF + (s & 1) * RING_SLOT;
            #pragma unroll
            for (int u = 0; u < 16; ++u) {
                const uint32_t sw = (uint32_t)((i << 1) ^ ((u & 7) << 4));
                const float xr = __half2float(*(const __half*)(st + u * 768 +   0 + sw));
                const float xz = __half2float(*(const __half*)(st + u * 768 + 256 + sw));
                const float xn = __half2float(*(const __half*)(st + u * 768 + 512 + sw));
                const float pr = fmaf(0.5f, xr, bhr_h);
                const float pz = fmaf(0.5f, xz, bhz_h);
                const float kk = fmaf(w_hn, hv, b_hn);
                const float r = fmaf(tanh_fast(fmaf(whr_h, hv, pr)), 0.5f, 0.5f);
                const float z = fmaf(tanh_fast(fmaf(whz_h, hv, pz)), 0.5f, 0.5f);
                const float n = tanh_fast(fmaf(r, kk, xn));
                hv = fmaf(z, hv - n, n);
                po[(size_t)(s * 16 + u) * OS] = hv;
            }
            BAR_ARRIVE(1 + (s & 1), 256);    // slot free
        }
        out[(size_t)T_LEN * OS + (size_t)b * HDIM + h] = hv;
    }
}

// ---------------------------------------------------------------------------
// Launch
// ---------------------------------------------------------------------------
extern "C" void kernel_launch(void* const* d_in, const int* in_sizes, int n_in,
                              void* d_out, int out_size)
{
    const float* x    = (const float*)d_in[0];   // [T, B, I]
    const float* W_ih = (const float*)d_in[1];   // [3H, I]
    const float* b_ih = (const float*)d_in[2];   // [3H]
    const float* b_hh = (const float*)d_in[3];   // [3H]
    const float* w_hh = (const float*)d_in[4];   // [3, H]
    float* out = (float*)d_out;

    static bool attr_done = false;
    if (!attr_done) {
        cudaFuncSetAttribute(indgru_fused,
                             cudaFuncAttributeMaxDynamicSharedMemorySize, FUSED_SMEM);
        attr_done = true;
    }

    convert_kernel<<<2048, 256>>>(x, W_ih);
    indgru_fused<<<128, 256, FUSED_SMEM>>>(b_ih, b_hh, w_hh, out);
}